// round 13
// baseline (speedup 1.0000x reference)
#include <cuda_runtime.h>
#include <cuda_bf16.h>
#include <mma.h>
#include <cstddef>
#include <cstdint>

using namespace nvcuda;

#define CDIV(a,b) (((a)+(b)-1)/(b))

constexpr int NU    = 50000;
constexpr int NR    = 20000;
constexpr int DIN   = 512;
constexpr int H     = 256;
constexpr int EREV  = 500000;
constexpr int ENEAR = 250000;
constexpr int NU_H1 = 25088;            // outU split point (196 * 128)

// ---------------- scratch (static device globals; no allocations) ----------
__device__ float g_tru1[(size_t)NR * H];
__device__ float g_tru2[(size_t)NR * H];
__device__ float g_huBf[(size_t)NU * H];
__device__ float g_hrAf[(size_t)NR * H];
__device__ float g_hrBf[(size_t)NR * H];
__device__ int   g_deg[NU + 3 * NR];
__device__ float g_inv_du[NU];
__device__ float g_inv_dr[NR];
__device__ float g_inv_ds[NR];
__device__ float g_inv_dd[NR];
// CSR buckets
__device__ int   g_offRD[NR + 1], g_offND[NR + 1], g_offRS[NU + 1];
__device__ int   g_curRD[NR],     g_curND[NR],     g_curRS[NU];
__device__ int   g_ndRD[EREV],   g_ndND[ENEAR],   g_ndRS[EREV];
__device__ float g_nmRD[EREV],   g_nmND[ENEAR],   g_nmRS[EREV];
// bf16 hi/lo GEMM operands
__device__ __nv_bfloat16 g_xrh[(size_t)NR * DIN], g_xrl[(size_t)NR * DIN];
__device__ __nv_bfloat16 g_huAh[(size_t)NU * H], g_huAl[(size_t)NU * H];
__device__ __nv_bfloat16 g_hrAh[(size_t)NR * H], g_hrAl[(size_t)NR * H];
__device__ __nv_bfloat16 g_hrBh[(size_t)NR * H], g_hrBl[(size_t)NR * H];
__device__ __nv_bfloat16 g_agg1h[(size_t)NR * 768], g_agg1l[(size_t)NR * 768];
__device__ __nv_bfloat16 g_agg2h[(size_t)NR * 512], g_agg2l[(size_t)NR * 512];
constexpr int WTOT = 917504;
__device__ __nv_bfloat16 g_wh[WTOT], g_wl[WTOT];

// ---------------- helpers ----------------------------------------------------
__device__ __forceinline__ uint32_t smem_u32(const void* p) {
    uint32_t a;
    asm("{ .reg .u64 t; cvta.to.shared.u64 t, %1; cvt.u32.u64 %0, t; }" : "=r"(a) : "l"(p));
    return a;
}
__device__ __forceinline__ void cp16(uint32_t dst, const void* src, bool ok) {
    int sz = ok ? 16 : 0;
    asm volatile("cp.async.cg.shared.global [%0], [%1], 16, %2;"
                 :: "r"(dst), "l"(src), "r"(sz) : "memory");
}
#define CP_COMMIT() asm volatile("cp.async.commit_group;" ::: "memory")
#define CP_WAIT1()  asm volatile("cp.async.wait_group 1;" ::: "memory")

__device__ __forceinline__ uint2 split_pack(float4 v) {
    __nv_bfloat16 h0 = __float2bfloat16_rn(v.x), h1 = __float2bfloat16_rn(v.y);
    __nv_bfloat16 h2 = __float2bfloat16_rn(v.z), h3 = __float2bfloat16_rn(v.w);
    __nv_bfloat162 a = __halves2bfloat162(h0, h1);
    __nv_bfloat162 b = __halves2bfloat162(h2, h3);
    uint2 r;
    r.x = *(uint32_t*)&a; r.y = *(uint32_t*)&b;
    return r;
}
__device__ __forceinline__ uint2 split_pack_lo(float4 v, uint2 hi) {
    __nv_bfloat162 a = *(__nv_bfloat162*)&hi.x;
    __nv_bfloat162 b = *(__nv_bfloat162*)&hi.y;
    float4 r = make_float4(v.x - __bfloat162float(__low2bfloat16(a)),
                           v.y - __bfloat162float(__high2bfloat16(a)),
                           v.z - __bfloat162float(__low2bfloat16(b)),
                           v.w - __bfloat162float(__high2bfloat16(b)));
    return split_pack(r);
}

// ---------------- split kernel ------------------------------------------------
__global__ void split_bf16(const float* __restrict__ in,
                           __nv_bfloat16* __restrict__ h,
                           __nv_bfloat16* __restrict__ l, int n4) {
    int i = blockIdx.x * 256 + threadIdx.x;
    if (i >= n4) return;
    float4 v = ((const float4*)in)[i];
    uint2 hi = split_pack(v);
    uint2 lo = split_pack_lo(v, hi);
    ((uint2*)h)[i] = hi;
    ((uint2*)l)[i] = lo;
}

// ---------------- double-buffered bf16-split wmma GEMM ----------------------
constexpr int BM = 128, BN = 256, BK = 32;
constexpr int LDA = BK + 8;
constexpr int LDB = BN + 8;
constexpr int E_AH = 0;
constexpr int E_AL = E_AH + BM * LDA;
constexpr int E_BH = E_AL + BM * LDA;
constexpr int E_BL = E_BH + BK * LDB;
constexpr int STAGE_E = E_BL + BK * LDB;
constexpr int GEMM_SMEM = 2 * STAGE_E * 2;

__global__ __launch_bounds__(256, 1) void wgemm2(const __nv_bfloat16* __restrict__ Ahg,
                                                 const __nv_bfloat16* __restrict__ Alg,
                                                 const __nv_bfloat16* __restrict__ Bhg,
                                                 const __nv_bfloat16* __restrict__ Blg,
                                                 float* __restrict__ C,
                                                 __nv_bfloat16* __restrict__ Ch,
                                                 __nv_bfloat16* __restrict__ Cl,
                                                 float* __restrict__ Cf,
                                                 const float* __restrict__ bias0,
                                                 const float* __restrict__ bias1,
                                                 int do_relu,
                                                 int M, int K) {
    extern __shared__ __nv_bfloat16 sm[];
    uint32_t sbase = smem_u32(sm);

    int tid  = threadIdx.x;
    int wid  = tid >> 5;
    int lane = tid & 31;
    int row0 = blockIdx.y * BM;
    int wm   = wid >> 2;
    int wn   = wid & 3;

    wmma::fragment<wmma::accumulator, 16, 16, 16, float> acc[4][4];
#pragma unroll
    for (int mi = 0; mi < 4; mi++)
#pragma unroll
        for (int ni = 0; ni < 4; ni++) wmma::fill_fragment(acc[mi][ni], 0.f);

    auto load_stage = [&](int st, int k0) {
        uint32_t base = sbase + st * (STAGE_E * 2);
#pragma unroll
        for (int q = 0; q < 2; q++) {
            int i   = tid + 256 * q;
            int row = i >> 2;
            int c8  = (i & 3) << 3;
            bool ok = (row0 + row) < M;
            size_t off = (size_t)(ok ? row0 + row : 0) * K + k0 + c8;
            uint32_t d = base + (row * LDA + c8) * 2;
            cp16(d, Ahg + off, ok);
            cp16(d + E_AL * 2, Alg + off, ok);
        }
#pragma unroll
        for (int q = 0; q < 4; q++) {
            int i  = tid + 256 * q;
            int kk = i >> 5;
            int c8 = (i & 31) << 3;
            size_t off = (size_t)(k0 + kk) * 256 + c8;
            uint32_t d = base + E_BH * 2 + (kk * LDB + c8) * 2;
            cp16(d, Bhg + off, true);
            cp16(d + (E_BL - E_BH) * 2, Blg + off, true);
        }
    };

    int NC = K / BK;
    load_stage(0, 0);
    CP_COMMIT();

    for (int c = 0; c < NC; c++) {
        if (c + 1 < NC) load_stage((c + 1) & 1, (c + 1) * BK);
        CP_COMMIT();
        CP_WAIT1();
        __syncthreads();

        const __nv_bfloat16* sAh = sm + (c & 1) * STAGE_E + E_AH;
        const __nv_bfloat16* sAl = sm + (c & 1) * STAGE_E + E_AL;
        const __nv_bfloat16* sBh = sm + (c & 1) * STAGE_E + E_BH;
        const __nv_bfloat16* sBl = sm + (c & 1) * STAGE_E + E_BL;

#pragma unroll
        for (int kk = 0; kk < BK; kk += 16) {
            wmma::fragment<wmma::matrix_a, 16, 16, 16, __nv_bfloat16, wmma::row_major> ah[4], al[4];
#pragma unroll
            for (int mi = 0; mi < 4; mi++) {
                wmma::load_matrix_sync(ah[mi], sAh + (wm * 64 + mi * 16) * LDA + kk, LDA);
                wmma::load_matrix_sync(al[mi], sAl + (wm * 64 + mi * 16) * LDA + kk, LDA);
            }
#pragma unroll
            for (int ni = 0; ni < 4; ni++) {
                wmma::fragment<wmma::matrix_b, 16, 16, 16, __nv_bfloat16, wmma::row_major> bh, bl;
                wmma::load_matrix_sync(bh, sBh + kk * LDB + wn * 64 + ni * 16, LDB);
                wmma::load_matrix_sync(bl, sBl + kk * LDB + wn * 64 + ni * 16, LDB);
#pragma unroll
                for (int mi = 0; mi < 4; mi++) {
                    wmma::mma_sync(acc[mi][ni], ah[mi], bh, acc[mi][ni]);
                    wmma::mma_sync(acc[mi][ni], al[mi], bh, acc[mi][ni]);
                    wmma::mma_sync(acc[mi][ni], ah[mi], bl, acc[mi][ni]);
                }
            }
        }
        __syncthreads();
    }

    if (Ch != nullptr) {
        float* stage = (float*)sm + wid * 512;
#pragma unroll
        for (int mi = 0; mi < 4; mi++)
#pragma unroll
            for (int ni = 0; ni < 4; ni++) {
                wmma::store_matrix_sync(stage, acc[mi][ni], 20, wmma::mem_row_major);
                __syncwarp();
#pragma unroll
                for (int jj = 0; jj < 4; jj++) {
                    int e2 = lane * 4 + jj;
                    int r  = e2 >> 3;
                    int c0 = (e2 & 7) * 2;
                    int row = row0 + wm * 64 + mi * 16 + r;
                    if (row < M) {
                        int col = wn * 64 + ni * 16 + c0;
                        float v0 = stage[r * 20 + c0], v1 = stage[r * 20 + c0 + 1];
                        if (bias0) { v0 += bias0[col]; v1 += bias0[col + 1]; }
                        if (bias1) { v0 += bias1[col]; v1 += bias1[col + 1]; }
                        if (do_relu) { v0 = fmaxf(v0, 0.f); v1 = fmaxf(v1, 0.f); }
                        __nv_bfloat16 h0 = __float2bfloat16_rn(v0);
                        __nv_bfloat16 h1 = __float2bfloat16_rn(v1);
                        __nv_bfloat16 l0 = __float2bfloat16_rn(v0 - __bfloat162float(h0));
                        __nv_bfloat16 l1 = __float2bfloat16_rn(v1 - __bfloat162float(h1));
                        size_t off = (size_t)row * 256 + col;
                        *(__nv_bfloat162*)(Ch + off) = __halves2bfloat162(h0, h1);
                        *(__nv_bfloat162*)(Cl + off) = __halves2bfloat162(l0, l1);
                        if (Cf) { Cf[off] = v0; Cf[off + 1] = v1; }
                    }
                }
                __syncwarp();
            }
    } else if (row0 + BM <= M) {
#pragma unroll
        for (int mi = 0; mi < 4; mi++)
#pragma unroll
            for (int ni = 0; ni < 4; ni++) {
                float* cp = C + (size_t)(row0 + wm * 64 + mi * 16) * 256
                              + wn * 64 + ni * 16;
                wmma::store_matrix_sync(cp, acc[mi][ni], 256, wmma::mem_row_major);
            }
    } else {
        float* stage = (float*)sm + wid * 512;
#pragma unroll
        for (int mi = 0; mi < 4; mi++)
#pragma unroll
            for (int ni = 0; ni < 4; ni++) {
                wmma::store_matrix_sync(stage, acc[mi][ni], 20, wmma::mem_row_major);
                __syncwarp();
#pragma unroll
                for (int j = 0; j < 8; j++) {
                    int e   = lane * 8 + j;
                    int r   = e >> 4, cc = e & 15;
                    int row = row0 + wm * 64 + mi * 16 + r;
                    if (row < M)
                        C[(size_t)row * 256 + wn * 64 + ni * 16 + cc] =
                            stage[r * 20 + cc];
                }
                __syncwarp();
            }
    }
}

// ---------------- CSR build kernels -----------------------------------------
__global__ void count_deg(const int* __restrict__ idx, int* __restrict__ deg, int E) {
    int i = blockIdx.x * 256 + threadIdx.x;
    if (i < E) atomicAdd(&deg[idx[i]], 1);
}

__global__ void make_inv(const int* __restrict__ deg, float* __restrict__ inv, int n, int add) {
    int i = blockIdx.x * 256 + threadIdx.x;
    if (i < n) {
        int d = deg[i] + add;
        inv[i] = d > 0 ? rsqrtf((float)d) : 0.f;
    }
}

__global__ __launch_bounds__(1024) void scan3(const int* c0, int* o0, int n0,
                                              const int* c1, int* o1, int n1,
                                              const int* c2, int* o2, int n2) {
    const int* cnt = blockIdx.x == 0 ? c0 : blockIdx.x == 1 ? c1 : c2;
    int* off = blockIdx.x == 0 ? o0 : blockIdx.x == 1 ? o1 : o2;
    int n    = blockIdx.x == 0 ? n0 : blockIdx.x == 1 ? n1 : n2;
    __shared__ int tmp[1024];
    __shared__ int carry;
    if (threadIdx.x == 0) carry = 0;
    __syncthreads();
    for (int base = 0; base < n; base += 1024) {
        int i = base + (int)threadIdx.x;
        int v = (i < n) ? cnt[i] : 0;
        tmp[threadIdx.x] = v;
        __syncthreads();
#pragma unroll
        for (int s = 1; s < 1024; s <<= 1) {
            int t = (threadIdx.x >= (unsigned)s) ? tmp[threadIdx.x - s] : 0;
            __syncthreads();
            tmp[threadIdx.x] += t;
            __syncthreads();
        }
        if (i < n) off[i] = carry + tmp[threadIdx.x] - v;
        __syncthreads();
        if (threadIdx.x == 0) carry += tmp[1023];
        __syncthreads();
    }
    if (threadIdx.x == 0) off[n] = carry;
}

__global__ void fill_bucket(const int* __restrict__ key, const int* __restrict__ other,
                            const float* __restrict__ inv_k, const float* __restrict__ inv_o,
                            int* __restrict__ cursor,
                            int* __restrict__ nodes, float* __restrict__ norms, int E) {
    int i = blockIdx.x * 256 + threadIdx.x;
    if (i >= E) return;
    int k = key[i], o = other[i];
    int pos = atomicAdd(&cursor[k], 1);
    nodes[pos] = o;
    norms[pos] = inv_k[k] * inv_o[o];
}

// ---------------- gathers -----------------------------------------------------
// raw-input ur aggregation, 2-edge unrolled for MLP
__global__ __launch_bounds__(128) void gather_aggX(const float* __restrict__ xu,
                                                   __nv_bfloat16* __restrict__ aggh,
                                                   __nv_bfloat16* __restrict__ aggl) {
    int row = blockIdx.x;
    int c   = threadIdx.x;
    float4 acc = make_float4(0.f, 0.f, 0.f, 0.f);
    int e = g_offRD[row], e1 = g_offRD[row + 1];
    for (; e + 1 < e1; e += 2) {
        int s0 = g_ndRD[e], s1 = g_ndRD[e + 1];
        float n0 = g_nmRD[e], n1 = g_nmRD[e + 1];
        float4 v0 = ((const float4*)xu)[(size_t)s0 * 128 + c];
        float4 v1 = ((const float4*)xu)[(size_t)s1 * 128 + c];
        acc.x += v0.x * n0 + v1.x * n1; acc.y += v0.y * n0 + v1.y * n1;
        acc.z += v0.z * n0 + v1.z * n1; acc.w += v0.w * n0 + v1.w * n1;
    }
    if (e < e1) {
        int s = g_ndRD[e]; float n = g_nmRD[e];
        float4 v = ((const float4*)xu)[(size_t)s * 128 + c];
        acc.x += v.x * n; acc.y += v.y * n; acc.z += v.z * n; acc.w += v.w * n;
    }
    uint2 hi = split_pack(acc);
    uint2 lo = split_pack_lo(acc, hi);
    ((uint2*)aggh)[(size_t)row * 192 + c] = hi;
    ((uint2*)aggl)[(size_t)row * 192 + c] = lo;
}

__global__ __launch_bounds__(64) void gather_aggU(const float* __restrict__ huf,
                                                  __nv_bfloat16* __restrict__ aggh,
                                                  __nv_bfloat16* __restrict__ aggl,
                                                  int stride_u2, int off_u2) {
    int row = blockIdx.x;
    int c   = threadIdx.x;
    float4 acc = make_float4(0.f, 0.f, 0.f, 0.f);
    int e = g_offRD[row], e1 = g_offRD[row + 1];
    for (; e + 1 < e1; e += 2) {
        int s0 = g_ndRD[e], s1 = g_ndRD[e + 1];
        float n0 = g_nmRD[e], n1 = g_nmRD[e + 1];
        float4 v0 = ((const float4*)huf)[(size_t)s0 * 64 + c];
        float4 v1 = ((const float4*)huf)[(size_t)s1 * 64 + c];
        acc.x += v0.x * n0 + v1.x * n1; acc.y += v0.y * n0 + v1.y * n1;
        acc.z += v0.z * n0 + v1.z * n1; acc.w += v0.w * n0 + v1.w * n1;
    }
    if (e < e1) {
        int s0 = g_ndRD[e]; float n0 = g_nmRD[e];
        float4 v0 = ((const float4*)huf)[(size_t)s0 * 64 + c];
        acc.x += v0.x * n0; acc.y += v0.y * n0; acc.z += v0.z * n0; acc.w += v0.w * n0;
    }
    uint2 hi = split_pack(acc);
    uint2 lo = split_pack_lo(acc, hi);
    ((uint2*)aggh)[(size_t)row * stride_u2 + off_u2 + c] = hi;
    ((uint2*)aggl)[(size_t)row * stride_u2 + off_u2 + c] = lo;
}

__global__ __launch_bounds__(64) void gather_aggRR(const float* __restrict__ hrf,
                                                   __nv_bfloat16* __restrict__ aggh,
                                                   __nv_bfloat16* __restrict__ aggl,
                                                   int stride_u2, int off_u2) {
    int row = blockIdx.x;
    int c   = threadIdx.x;
    float coef = g_inv_ds[row] * g_inv_dd[row];
    float4 own = ((const float4*)hrf)[(size_t)row * 64 + c];
    float4 acc = make_float4(own.x * coef, own.y * coef, own.z * coef, own.w * coef);
    int e = g_offND[row], e1 = g_offND[row + 1];
    for (; e + 1 < e1; e += 2) {
        int s0 = g_ndND[e], s1 = g_ndND[e + 1];
        float n0 = g_nmND[e], n1 = g_nmND[e + 1];
        float4 v0 = ((const float4*)hrf)[(size_t)s0 * 64 + c];
        float4 v1 = ((const float4*)hrf)[(size_t)s1 * 64 + c];
        acc.x += v0.x * n0 + v1.x * n1; acc.y += v0.y * n0 + v1.y * n1;
        acc.z += v0.z * n0 + v1.z * n1; acc.w += v0.w * n0 + v1.w * n1;
    }
    if (e < e1) {
        int s0 = g_ndND[e]; float n0 = g_nmND[e];
        float4 v0 = ((const float4*)hrf)[(size_t)s0 * 64 + c];
        acc.x += v0.x * n0; acc.y += v0.y * n0; acc.z += v0.z * n0; acc.w += v0.w * n0;
    }
    uint2 hi = split_pack(acc);
    uint2 lo = split_pack_lo(acc, hi);
    ((uint2*)aggh)[(size_t)row * stride_u2 + off_u2 + c] = hi;
    ((uint2*)aggl)[(size_t)row * stride_u2 + off_u2 + c] = lo;
}

__global__ __launch_bounds__(64) void gather_user(const float* __restrict__ tru,
                                                  const float* __restrict__ bru,
                                                  __nv_bfloat16* __restrict__ hh,
                                                  __nv_bfloat16* __restrict__ hl,
                                                  float* __restrict__ hf) {
    int row = blockIdx.x;
    int c   = threadIdx.x;
    float4 acc = ((const float4*)bru)[c];

    int e = g_offRS[row], e1 = g_offRS[row + 1];
    for (; e + 1 < e1; e += 2) {
        int s0 = g_ndRS[e], s1 = g_ndRS[e + 1];
        float n0 = g_nmRS[e], n1 = g_nmRS[e + 1];
        float4 v0 = ((const float4*)tru)[(size_t)s0 * 64 + c];
        float4 v1 = ((const float4*)tru)[(size_t)s1 * 64 + c];
        acc.x += v0.x * n0 + v1.x * n1; acc.y += v0.y * n0 + v1.y * n1;
        acc.z += v0.z * n0 + v1.z * n1; acc.w += v0.w * n0 + v1.w * n1;
    }
    if (e < e1) {
        int s0 = g_ndRS[e]; float n0 = g_nmRS[e];
        float4 v0 = ((const float4*)tru)[(size_t)s0 * 64 + c];
        acc.x += v0.x * n0; acc.y += v0.y * n0; acc.z += v0.z * n0; acc.w += v0.w * n0;
    }

    acc = make_float4(fmaxf(acc.x, 0.f), fmaxf(acc.y, 0.f),
                      fmaxf(acc.z, 0.f), fmaxf(acc.w, 0.f));
    if (hh) {
        uint2 hi = split_pack(acc);
        uint2 lo = split_pack_lo(acc, hi);
        ((uint2*)hh)[(size_t)row * 64 + c] = hi;
        ((uint2*)hl)[(size_t)row * 64 + c] = lo;
    }
    if (hf) ((float4*)hf)[(size_t)row * 64 + c] = acc;
}

// ---------------- host orchestration ----------------------------------------
extern "C" void kernel_launch(void* const* d_in, const int* in_sizes, int n_in,
                              void* d_out, int out_size) {
    const float* x_user    = (const float*)d_in[0];
    const float* x_rest    = (const float*)d_in[1];
    const int*   rev_src   = (const int*)d_in[2];
    const int*   rev_dst   = (const int*)d_in[3];
    const int*   near_src  = (const int*)d_in[4];
    const int*   near_dst  = (const int*)d_in[5];
    const float* Win_user  = (const float*)d_in[6];
    const float* Win_rest  = (const float*)d_in[7];
    const float* W1_ur = (const float*)d_in[8];
    const float* b1_ur = (const float*)d_in[9];
    const float* W1_ru = (const float*)d_in[10];
    const float* b1_ru = (const float*)d_in[11];
    const float* W1_rr = (const float*)d_in[12];
    const float* b1_rr = (const float*)d_in[13];
    const float* W2_ur = (const float*)d_in[14];
    const float* b2_ur = (const float*)d_in[15];
    const float* W2_ru = (const float*)d_in[16];
    const float* b2_ru = (const float*)d_in[17];
    const float* W2_rr = (const float*)d_in[18];
    const float* b2_rr = (const float*)d_in[19];
    const float* Wout_user = (const float*)d_in[20];
    const float* Wout_rest = (const float*)d_in[21];

    cudaFuncSetAttribute(wgemm2, cudaFuncAttributeMaxDynamicSharedMemorySize, GEMM_SMEM);

    static cudaStream_t s2 = nullptr;
    static cudaEvent_t evFork, evPR, evT1, evR1, evT2, evAG1, evAG2, evGU2, evJoin;
    if (!s2) {
        cudaStreamCreateWithFlags(&s2, cudaStreamNonBlocking);
        cudaEventCreateWithFlags(&evFork, cudaEventDisableTiming);
        cudaEventCreateWithFlags(&evPR,   cudaEventDisableTiming);
        cudaEventCreateWithFlags(&evT1,   cudaEventDisableTiming);
        cudaEventCreateWithFlags(&evR1,   cudaEventDisableTiming);
        cudaEventCreateWithFlags(&evT2,   cudaEventDisableTiming);
        cudaEventCreateWithFlags(&evAG1,  cudaEventDisableTiming);
        cudaEventCreateWithFlags(&evAG2,  cudaEventDisableTiming);
        cudaEventCreateWithFlags(&evGU2,  cudaEventDisableTiming);
        cudaEventCreateWithFlags(&evJoin, cudaEventDisableTiming);
    }

    float *tru1, *tru2, *huBf, *hrAf, *hrBf;
    float *inv_du, *inv_dr, *inv_ds, *inv_dd;
    int *deg, *offRD, *offND, *offRS, *curRD, *curND, *curRS, *ndRD, *ndND, *ndRS;
    float *nmRD, *nmND, *nmRS;
    __nv_bfloat16 *xrh, *xrl, *wh, *wl, *agg1h, *agg1l, *agg2h, *agg2l;
    __nv_bfloat16 *huAh, *huAl, *hrAh, *hrAl, *hrBh, *hrBl;
    cudaGetSymbolAddress((void**)&tru1, g_tru1);
    cudaGetSymbolAddress((void**)&tru2, g_tru2);
    cudaGetSymbolAddress((void**)&huBf, g_huBf);
    cudaGetSymbolAddress((void**)&hrAf, g_hrAf);
    cudaGetSymbolAddress((void**)&hrBf, g_hrBf);
    cudaGetSymbolAddress((void**)&inv_du, g_inv_du);
    cudaGetSymbolAddress((void**)&inv_dr, g_inv_dr);
    cudaGetSymbolAddress((void**)&inv_ds, g_inv_ds);
    cudaGetSymbolAddress((void**)&inv_dd, g_inv_dd);
    cudaGetSymbolAddress((void**)&deg, g_deg);
    cudaGetSymbolAddress((void**)&offRD, g_offRD);
    cudaGetSymbolAddress((void**)&offND, g_offND);
    cudaGetSymbolAddress((void**)&offRS, g_offRS);
    cudaGetSymbolAddress((void**)&curRD, g_curRD);
    cudaGetSymbolAddress((void**)&curND, g_curND);
    cudaGetSymbolAddress((void**)&curRS, g_curRS);
    cudaGetSymbolAddress((void**)&ndRD, g_ndRD);
    cudaGetSymbolAddress((void**)&ndND, g_ndND);
    cudaGetSymbolAddress((void**)&ndRS, g_ndRS);
    cudaGetSymbolAddress((void**)&nmRD, g_nmRD);
    cudaGetSymbolAddress((void**)&nmND, g_nmND);
    cudaGetSymbolAddress((void**)&nmRS, g_nmRS);
    cudaGetSymbolAddress((void**)&xrh, g_xrh);
    cudaGetSymbolAddress((void**)&xrl, g_xrl);
    cudaGetSymbolAddress((void**)&huAh, g_huAh);
    cudaGetSymbolAddress((void**)&huAl, g_huAl);
    cudaGetSymbolAddress((void**)&hrAh, g_hrAh);
    cudaGetSymbolAddress((void**)&hrAl, g_hrAl);
    cudaGetSymbolAddress((void**)&hrBh, g_hrBh);
    cudaGetSymbolAddress((void**)&hrBl, g_hrBl);
    cudaGetSymbolAddress((void**)&agg1h, g_agg1h);
    cudaGetSymbolAddress((void**)&agg1l, g_agg1l);
    cudaGetSymbolAddress((void**)&agg2h, g_agg2h);
    cudaGetSymbolAddress((void**)&agg2l, g_agg2l);
    cudaGetSymbolAddress((void**)&wh, g_wh);
    cudaGetSymbolAddress((void**)&wl, g_wl);

    int* du = deg;
    int* dr = deg + NU;
    int* ds = dr + NR;
    int* dd = ds + NR;

    // weight scratch offsets (elems)
    const int O_WIN_U = 0;
    const int O_WIN_R = 131072;
    const int O_RU1   = 262144;
    const int O_RU2   = 327680;
    const int O_W1UR  = 393216;
    const int O_WCOMB = 458752;
    const int O_W1RR  = 589824;
    const int O_CAT2  = 655360;
    const int O_OUTU  = 786432;
    const int O_OUTR  = 851968;

    dim3 gR(1, CDIV(NR, BM));
    dim3 gW(1, CDIV(512, BM));
    dim3 gUa(1, CDIV(NU_H1, BM));          // 196 blocks
    dim3 gUb(1, CDIV(NU - NU_H1, BM));     // 195 blocks

    // ===== fork s2 =====
    cudaEventRecord(evFork, 0);
    cudaStreamWaitEvent(s2, evFork, 0);

    // ----- s2: weight/input splits, Wcomb, rest projection -----
    split_bf16<<<CDIV(DIN*H/4, 256), 256, 0, s2>>>(Win_user, wh + O_WIN_U, wl + O_WIN_U, DIN*H/4);
    split_bf16<<<CDIV(H*H/4, 256), 256, 0, s2>>>(W1_ur, wh + O_W1UR, wl + O_W1UR, H*H/4);
    split_bf16<<<CDIV(DIN*H/4, 256), 256, 0, s2>>>(Win_rest, wh + O_WIN_R, wl + O_WIN_R, DIN*H/4);
    split_bf16<<<CDIV(H*H/4, 256), 256, 0, s2>>>(W1_ru, wh + O_RU1, wl + O_RU1, H*H/4);
    split_bf16<<<CDIV(H*H/4, 256), 256, 0, s2>>>(W2_ru, wh + O_RU2, wl + O_RU2, H*H/4);
    split_bf16<<<CDIV(H*H/4, 256), 256, 0, s2>>>(W1_rr, wh + O_W1RR, wl + O_W1RR, H*H/4);
    split_bf16<<<CDIV(H*H/4, 256), 256, 0, s2>>>(W2_ur, wh + O_CAT2, wl + O_CAT2, H*H/4);
    split_bf16<<<CDIV(H*H/4, 256), 256, 0, s2>>>(W2_rr, wh + O_CAT2 + H*H, wl + O_CAT2 + H*H, H*H/4);
    split_bf16<<<CDIV(H*H/4, 256), 256, 0, s2>>>(Wout_user, wh + O_OUTU, wl + O_OUTU, H*H/4);
    split_bf16<<<CDIV(H*H/4, 256), 256, 0, s2>>>(Wout_rest, wh + O_OUTR, wl + O_OUTR, H*H/4);
    split_bf16<<<CDIV(NR*DIN/4, 256), 256, 0, s2>>>(x_rest, xrh, xrl, NR*DIN/4);
    wgemm2<<<gW, 256, GEMM_SMEM, s2>>>(wh + O_WIN_U, wl + O_WIN_U, wh + O_W1UR, wl + O_W1UR,
                                       nullptr, wh + O_WCOMB, wl + O_WCOMB, nullptr,
                                       nullptr, nullptr, 0, 512, 256);
    wgemm2<<<gR, 256, GEMM_SMEM, s2>>>(xrh, xrl, wh + O_WIN_R, wl + O_WIN_R,
                                       nullptr, hrAh, hrAl, hrAf,
                                       nullptr, nullptr, 0, NR, DIN);
    cudaEventRecord(evPR, s2);

    // ----- stream0: CSR build, then raw-input ur-gather -----
    cudaMemsetAsync(deg, 0, sizeof(int) * (NU + 3 * NR));
    count_deg<<<CDIV(EREV, 256), 256>>>(rev_src, du, EREV);
    count_deg<<<CDIV(EREV, 256), 256>>>(rev_dst, dr, EREV);
    count_deg<<<CDIV(ENEAR, 256), 256>>>(near_src, ds, ENEAR);
    count_deg<<<CDIV(ENEAR, 256), 256>>>(near_dst, dd, ENEAR);
    make_inv<<<CDIV(NU, 256), 256>>>(du, inv_du, NU, 0);
    make_inv<<<CDIV(NR, 256), 256>>>(dr, inv_dr, NR, 0);
    make_inv<<<CDIV(NR, 256), 256>>>(ds, inv_ds, NR, 1);
    make_inv<<<CDIV(NR, 256), 256>>>(dd, inv_dd, NR, 1);
    scan3<<<3, 1024>>>(dr, offRD, NR, dd, offND, NR, du, offRS, NU);
    cudaMemcpyAsync(curRD, offRD, sizeof(int) * NR, cudaMemcpyDeviceToDevice);
    cudaMemcpyAsync(curND, offND, sizeof(int) * NR, cudaMemcpyDeviceToDevice);
    cudaMemcpyAsync(curRS, offRS, sizeof(int) * NU, cudaMemcpyDeviceToDevice);
    fill_bucket<<<CDIV(EREV, 256), 256>>>(rev_dst, rev_src, inv_dr, inv_du, curRD, ndRD, nmRD, EREV);
    fill_bucket<<<CDIV(ENEAR, 256), 256>>>(near_dst, near_src, inv_dd, inv_ds, curND, ndND, nmND, ENEAR);
    fill_bucket<<<CDIV(EREV, 256), 256>>>(rev_src, rev_dst, inv_du, inv_dr, curRS, ndRS, nmRS, EREV);

    gather_aggX<<<NR, 128>>>(x_user, agg1h, agg1l);
    cudaStreamWaitEvent(0, evPR, 0);
    gather_aggRR<<<NR, 64>>>(hrAf, agg1h, agg1l, 192, 128);
    cudaEventRecord(evAG1, 0);

    // ----- s2: layer 1 GEMMs -----
    wgemm2<<<gR, 256, GEMM_SMEM, s2>>>(hrAh, hrAl, wh + O_RU1, wl + O_RU1,
                                       tru1, nullptr, nullptr, nullptr,
                                       nullptr, nullptr, 0, NR, H);
    cudaEventRecord(evT1, s2);
    cudaStreamWaitEvent(s2, evAG1, 0);
    wgemm2<<<gR, 256, GEMM_SMEM, s2>>>(agg1h, agg1l, wh + O_WCOMB, wl + O_WCOMB,
                                       nullptr, hrBh, hrBl, hrBf,
                                       b1_ur, b1_rr, 1, NR, 768);
    cudaEventRecord(evR1, s2);
    wgemm2<<<gR, 256, GEMM_SMEM, s2>>>(hrBh, hrBl, wh + O_RU2, wl + O_RU2,
                                       tru2, nullptr, nullptr, nullptr,
                                       nullptr, nullptr, 0, NR, H);
    cudaEventRecord(evT2, s2);

    // ----- stream0: user gather L1, agg gathers L2 -----
    cudaStreamWaitEvent(0, evT1, 0);
    gather_user<<<NU, 64>>>(tru1, b1_ru, nullptr, nullptr, huBf);
    cudaStreamWaitEvent(0, evR1, 0);
    gather_aggRR<<<NR, 64>>>(hrBf, agg2h, agg2l, 128, 64);
    gather_aggU<<<NR, 64>>>(huBf, agg2h, agg2l, 128, 0);
    cudaEventRecord(evAG2, 0);

    // ----- s2: layer 2 CAT GEMM + rest output -----
    cudaStreamWaitEvent(s2, evAG2, 0);
    wgemm2<<<gR, 256, GEMM_SMEM, s2>>>(agg2h, agg2l, wh + O_CAT2, wl + O_CAT2,
                                       nullptr, hrAh, hrAl, nullptr,
                                       b2_ur, b2_rr, 1, NR, 2 * H);
    float* out = (float*)d_out;
    wgemm2<<<gR, 256, GEMM_SMEM, s2>>>(hrAh, hrAl, wh + O_OUTR, wl + O_OUTR,
                                       out + (size_t)NU * H, nullptr, nullptr, nullptr,
                                       nullptr, nullptr, 0, NR, H);

    // ----- stream0: user gather L2, then outU split across both streams -----
    cudaStreamWaitEvent(0, evT2, 0);
    gather_user<<<NU, 64>>>(tru2, b2_ru, huAh, huAl, nullptr);
    cudaEventRecord(evGU2, 0);
    // stream0: rows [0, NU_H1)
    wgemm2<<<gUa, 256, GEMM_SMEM>>>(huAh, huAl, wh + O_OUTU, wl + O_OUTU,
                                    out, nullptr, nullptr, nullptr,
                                    nullptr, nullptr, 0, NU_H1, H);
    // s2: rows [NU_H1, NU) after its outR and the gather
    cudaStreamWaitEvent(s2, evGU2, 0);
    wgemm2<<<gUb, 256, GEMM_SMEM, s2>>>(huAh + (size_t)NU_H1 * H, huAl + (size_t)NU_H1 * H,
                                        wh + O_OUTU, wl + O_OUTU,
                                        out + (size_t)NU_H1 * H, nullptr, nullptr, nullptr,
                                        nullptr, nullptr, 0, NU - NU_H1, H);
    cudaEventRecord(evJoin, s2);
    cudaStreamWaitEvent(0, evJoin, 0);
}

// round 14
// speedup vs baseline: 1.0051x; 1.0051x over previous
#include <cuda_runtime.h>
#include <cuda_bf16.h>
#include <mma.h>
#include <cstddef>
#include <cstdint>

using namespace nvcuda;

#define CDIV(a,b) (((a)+(b)-1)/(b))

constexpr int NU    = 50000;
constexpr int NR    = 20000;
constexpr int DIN   = 512;
constexpr int H     = 256;
constexpr int EREV  = 500000;
constexpr int ENEAR = 250000;
constexpr int NU_H1 = 25088;            // row split point (196 * 128)

// ---------------- scratch (static device globals; no allocations) ----------
__device__ float g_tru1[(size_t)NR * H];
__device__ float g_tru2[(size_t)NR * H];
__device__ float g_huBf[(size_t)NU * H];
__device__ float g_hrAf[(size_t)NR * H];
__device__ float g_hrBf[(size_t)NR * H];
__device__ int   g_deg[NU + 3 * NR];
__device__ float g_inv_du[NU];
__device__ float g_inv_dr[NR];
__device__ float g_inv_ds[NR];
__device__ float g_inv_dd[NR];
// CSR buckets
__device__ int   g_offRD[NR + 1], g_offND[NR + 1], g_offRS[NU + 1];
__device__ int   g_curRD[NR],     g_curND[NR],     g_curRS[NU];
__device__ int   g_ndRD[EREV],   g_ndND[ENEAR],   g_ndRS[EREV];
__device__ float g_nmRD[EREV],   g_nmND[ENEAR],   g_nmRS[EREV];
// bf16 hi/lo GEMM operands
__device__ __nv_bfloat16 g_xrh[(size_t)NR * DIN], g_xrl[(size_t)NR * DIN];
__device__ __nv_bfloat16 g_huAh[(size_t)NU * H], g_huAl[(size_t)NU * H];
__device__ __nv_bfloat16 g_hrAh[(size_t)NR * H], g_hrAl[(size_t)NR * H];
__device__ __nv_bfloat16 g_hrBh[(size_t)NR * H], g_hrBl[(size_t)NR * H];
__device__ __nv_bfloat16 g_agg1h[(size_t)NR * 768], g_agg1l[(size_t)NR * 768];
__device__ __nv_bfloat16 g_agg2h[(size_t)NR * 512], g_agg2l[(size_t)NR * 512];
constexpr int WTOT = 917504;
__device__ __nv_bfloat16 g_wh[WTOT], g_wl[WTOT];

// ---------------- helpers ----------------------------------------------------
__device__ __forceinline__ uint32_t smem_u32(const void* p) {
    uint32_t a;
    asm("{ .reg .u64 t; cvta.to.shared.u64 t, %1; cvt.u32.u64 %0, t; }" : "=r"(a) : "l"(p));
    return a;
}
__device__ __forceinline__ void cp16(uint32_t dst, const void* src, bool ok) {
    int sz = ok ? 16 : 0;
    asm volatile("cp.async.cg.shared.global [%0], [%1], 16, %2;"
                 :: "r"(dst), "l"(src), "r"(sz) : "memory");
}
#define CP_COMMIT() asm volatile("cp.async.commit_group;" ::: "memory")
#define CP_WAIT1()  asm volatile("cp.async.wait_group 1;" ::: "memory")

__device__ __forceinline__ uint2 split_pack(float4 v) {
    __nv_bfloat16 h0 = __float2bfloat16_rn(v.x), h1 = __float2bfloat16_rn(v.y);
    __nv_bfloat16 h2 = __float2bfloat16_rn(v.z), h3 = __float2bfloat16_rn(v.w);
    __nv_bfloat162 a = __halves2bfloat162(h0, h1);
    __nv_bfloat162 b = __halves2bfloat162(h2, h3);
    uint2 r;
    r.x = *(uint32_t*)&a; r.y = *(uint32_t*)&b;
    return r;
}
__device__ __forceinline__ uint2 split_pack_lo(float4 v, uint2 hi) {
    __nv_bfloat162 a = *(__nv_bfloat162*)&hi.x;
    __nv_bfloat162 b = *(__nv_bfloat162*)&hi.y;
    float4 r = make_float4(v.x - __bfloat162float(__low2bfloat16(a)),
                           v.y - __bfloat162float(__high2bfloat16(a)),
                           v.z - __bfloat162float(__low2bfloat16(b)),
                           v.w - __bfloat162float(__high2bfloat16(b)));
    return split_pack(r);
}

// ---------------- split kernel ------------------------------------------------
__global__ void split_bf16(const float* __restrict__ in,
                           __nv_bfloat16* __restrict__ h,
                           __nv_bfloat16* __restrict__ l, int n4) {
    int i = blockIdx.x * 256 + threadIdx.x;
    if (i >= n4) return;
    float4 v = ((const float4*)in)[i];
    uint2 hi = split_pack(v);
    uint2 lo = split_pack_lo(v, hi);
    ((uint2*)h)[i] = hi;
    ((uint2*)l)[i] = lo;
}

// ---------------- double-buffered bf16-split wmma GEMM ----------------------
constexpr int BM = 128, BN = 256, BK = 32;
constexpr int LDA = BK + 8;
constexpr int LDB = BN + 8;
constexpr int E_AH = 0;
constexpr int E_AL = E_AH + BM * LDA;
constexpr int E_BH = E_AL + BM * LDA;
constexpr int E_BL = E_BH + BK * LDB;
constexpr int STAGE_E = E_BL + BK * LDB;
constexpr int GEMM_SMEM = 2 * STAGE_E * 2;

__global__ __launch_bounds__(256, 1) void wgemm2(const __nv_bfloat16* __restrict__ Ahg,
                                                 const __nv_bfloat16* __restrict__ Alg,
                                                 const __nv_bfloat16* __restrict__ Bhg,
                                                 const __nv_bfloat16* __restrict__ Blg,
                                                 float* __restrict__ C,
                                                 __nv_bfloat16* __restrict__ Ch,
                                                 __nv_bfloat16* __restrict__ Cl,
                                                 float* __restrict__ Cf,
                                                 const float* __restrict__ bias0,
                                                 const float* __restrict__ bias1,
                                                 int do_relu,
                                                 int M, int K) {
    extern __shared__ __nv_bfloat16 sm[];
    uint32_t sbase = smem_u32(sm);

    int tid  = threadIdx.x;
    int wid  = tid >> 5;
    int lane = tid & 31;
    int row0 = blockIdx.y * BM;
    int wm   = wid >> 2;
    int wn   = wid & 3;

    wmma::fragment<wmma::accumulator, 16, 16, 16, float> acc[4][4];
#pragma unroll
    for (int mi = 0; mi < 4; mi++)
#pragma unroll
        for (int ni = 0; ni < 4; ni++) wmma::fill_fragment(acc[mi][ni], 0.f);

    auto load_stage = [&](int st, int k0) {
        uint32_t base = sbase + st * (STAGE_E * 2);
#pragma unroll
        for (int q = 0; q < 2; q++) {
            int i   = tid + 256 * q;
            int row = i >> 2;
            int c8  = (i & 3) << 3;
            bool ok = (row0 + row) < M;
            size_t off = (size_t)(ok ? row0 + row : 0) * K + k0 + c8;
            uint32_t d = base + (row * LDA + c8) * 2;
            cp16(d, Ahg + off, ok);
            cp16(d + E_AL * 2, Alg + off, ok);
        }
#pragma unroll
        for (int q = 0; q < 4; q++) {
            int i  = tid + 256 * q;
            int kk = i >> 5;
            int c8 = (i & 31) << 3;
            size_t off = (size_t)(k0 + kk) * 256 + c8;
            uint32_t d = base + E_BH * 2 + (kk * LDB + c8) * 2;
            cp16(d, Bhg + off, true);
            cp16(d + (E_BL - E_BH) * 2, Blg + off, true);
        }
    };

    int NC = K / BK;
    load_stage(0, 0);
    CP_COMMIT();

    for (int c = 0; c < NC; c++) {
        if (c + 1 < NC) load_stage((c + 1) & 1, (c + 1) * BK);
        CP_COMMIT();
        CP_WAIT1();
        __syncthreads();

        const __nv_bfloat16* sAh = sm + (c & 1) * STAGE_E + E_AH;
        const __nv_bfloat16* sAl = sm + (c & 1) * STAGE_E + E_AL;
        const __nv_bfloat16* sBh = sm + (c & 1) * STAGE_E + E_BH;
        const __nv_bfloat16* sBl = sm + (c & 1) * STAGE_E + E_BL;

#pragma unroll
        for (int kk = 0; kk < BK; kk += 16) {
            wmma::fragment<wmma::matrix_a, 16, 16, 16, __nv_bfloat16, wmma::row_major> ah[4], al[4];
#pragma unroll
            for (int mi = 0; mi < 4; mi++) {
                wmma::load_matrix_sync(ah[mi], sAh + (wm * 64 + mi * 16) * LDA + kk, LDA);
                wmma::load_matrix_sync(al[mi], sAl + (wm * 64 + mi * 16) * LDA + kk, LDA);
            }
#pragma unroll
            for (int ni = 0; ni < 4; ni++) {
                wmma::fragment<wmma::matrix_b, 16, 16, 16, __nv_bfloat16, wmma::row_major> bh, bl;
                wmma::load_matrix_sync(bh, sBh + kk * LDB + wn * 64 + ni * 16, LDB);
                wmma::load_matrix_sync(bl, sBl + kk * LDB + wn * 64 + ni * 16, LDB);
#pragma unroll
                for (int mi = 0; mi < 4; mi++) {
                    wmma::mma_sync(acc[mi][ni], ah[mi], bh, acc[mi][ni]);
                    wmma::mma_sync(acc[mi][ni], al[mi], bh, acc[mi][ni]);
                    wmma::mma_sync(acc[mi][ni], ah[mi], bl, acc[mi][ni]);
                }
            }
        }
        __syncthreads();
    }

    if (Ch != nullptr) {
        float* stage = (float*)sm + wid * 512;
#pragma unroll
        for (int mi = 0; mi < 4; mi++)
#pragma unroll
            for (int ni = 0; ni < 4; ni++) {
                wmma::store_matrix_sync(stage, acc[mi][ni], 20, wmma::mem_row_major);
                __syncwarp();
#pragma unroll
                for (int jj = 0; jj < 4; jj++) {
                    int e2 = lane * 4 + jj;
                    int r  = e2 >> 3;
                    int c0 = (e2 & 7) * 2;
                    int row = row0 + wm * 64 + mi * 16 + r;
                    if (row < M) {
                        int col = wn * 64 + ni * 16 + c0;
                        float v0 = stage[r * 20 + c0], v1 = stage[r * 20 + c0 + 1];
                        if (bias0) { v0 += bias0[col]; v1 += bias0[col + 1]; }
                        if (bias1) { v0 += bias1[col]; v1 += bias1[col + 1]; }
                        if (do_relu) { v0 = fmaxf(v0, 0.f); v1 = fmaxf(v1, 0.f); }
                        __nv_bfloat16 h0 = __float2bfloat16_rn(v0);
                        __nv_bfloat16 h1 = __float2bfloat16_rn(v1);
                        __nv_bfloat16 l0 = __float2bfloat16_rn(v0 - __bfloat162float(h0));
                        __nv_bfloat16 l1 = __float2bfloat16_rn(v1 - __bfloat162float(h1));
                        size_t off = (size_t)row * 256 + col;
                        *(__nv_bfloat162*)(Ch + off) = __halves2bfloat162(h0, h1);
                        *(__nv_bfloat162*)(Cl + off) = __halves2bfloat162(l0, l1);
                        if (Cf) { Cf[off] = v0; Cf[off + 1] = v1; }
                    }
                }
                __syncwarp();
            }
    } else if (row0 + BM <= M) {
#pragma unroll
        for (int mi = 0; mi < 4; mi++)
#pragma unroll
            for (int ni = 0; ni < 4; ni++) {
                float* cp = C + (size_t)(row0 + wm * 64 + mi * 16) * 256
                              + wn * 64 + ni * 16;
                wmma::store_matrix_sync(cp, acc[mi][ni], 256, wmma::mem_row_major);
            }
    } else {
        float* stage = (float*)sm + wid * 512;
#pragma unroll
        for (int mi = 0; mi < 4; mi++)
#pragma unroll
            for (int ni = 0; ni < 4; ni++) {
                wmma::store_matrix_sync(stage, acc[mi][ni], 20, wmma::mem_row_major);
                __syncwarp();
#pragma unroll
                for (int j = 0; j < 8; j++) {
                    int e   = lane * 8 + j;
                    int r   = e >> 4, cc = e & 15;
                    int row = row0 + wm * 64 + mi * 16 + r;
                    if (row < M)
                        C[(size_t)row * 256 + wn * 64 + ni * 16 + cc] =
                            stage[r * 20 + cc];
                }
                __syncwarp();
            }
    }
}

// ---------------- CSR build kernels -----------------------------------------
__global__ void count_deg(const int* __restrict__ idx, int* __restrict__ deg, int E) {
    int i = blockIdx.x * 256 + threadIdx.x;
    if (i < E) atomicAdd(&deg[idx[i]], 1);
}

__global__ void make_inv(const int* __restrict__ deg, float* __restrict__ inv, int n, int add) {
    int i = blockIdx.x * 256 + threadIdx.x;
    if (i < n) {
        int d = deg[i] + add;
        inv[i] = d > 0 ? rsqrtf((float)d) : 0.f;
    }
}

__global__ __launch_bounds__(1024) void scan3(const int* c0, int* o0, int n0,
                                              const int* c1, int* o1, int n1,
                                              const int* c2, int* o2, int n2) {
    const int* cnt = blockIdx.x == 0 ? c0 : blockIdx.x == 1 ? c1 : c2;
    int* off = blockIdx.x == 0 ? o0 : blockIdx.x == 1 ? o1 : o2;
    int n    = blockIdx.x == 0 ? n0 : blockIdx.x == 1 ? n1 : n2;
    __shared__ int tmp[1024];
    __shared__ int carry;
    if (threadIdx.x == 0) carry = 0;
    __syncthreads();
    for (int base = 0; base < n; base += 1024) {
        int i = base + (int)threadIdx.x;
        int v = (i < n) ? cnt[i] : 0;
        tmp[threadIdx.x] = v;
        __syncthreads();
#pragma unroll
        for (int s = 1; s < 1024; s <<= 1) {
            int t = (threadIdx.x >= (unsigned)s) ? tmp[threadIdx.x - s] : 0;
            __syncthreads();
            tmp[threadIdx.x] += t;
            __syncthreads();
        }
        if (i < n) off[i] = carry + tmp[threadIdx.x] - v;
        __syncthreads();
        if (threadIdx.x == 0) carry += tmp[1023];
        __syncthreads();
    }
    if (threadIdx.x == 0) off[n] = carry;
}

__global__ void fill_bucket(const int* __restrict__ key, const int* __restrict__ other,
                            const float* __restrict__ inv_k, const float* __restrict__ inv_o,
                            int* __restrict__ cursor,
                            int* __restrict__ nodes, float* __restrict__ norms, int E) {
    int i = blockIdx.x * 256 + threadIdx.x;
    if (i >= E) return;
    int k = key[i], o = other[i];
    int pos = atomicAdd(&cursor[k], 1);
    nodes[pos] = o;
    norms[pos] = inv_k[k] * inv_o[o];
}

// ---------------- gathers -----------------------------------------------------
__global__ __launch_bounds__(128) void gather_aggX(const float* __restrict__ xu,
                                                   __nv_bfloat16* __restrict__ aggh,
                                                   __nv_bfloat16* __restrict__ aggl) {
    int row = blockIdx.x;
    int c   = threadIdx.x;
    float4 acc = make_float4(0.f, 0.f, 0.f, 0.f);
    int e = g_offRD[row], e1 = g_offRD[row + 1];
    for (; e < e1; e++) {
        int s = g_ndRD[e];
        float n = g_nmRD[e];
        float4 v = ((const float4*)xu)[(size_t)s * 128 + c];
        acc.x += v.x * n; acc.y += v.y * n; acc.z += v.z * n; acc.w += v.w * n;
    }
    uint2 hi = split_pack(acc);
    uint2 lo = split_pack_lo(acc, hi);
    ((uint2*)aggh)[(size_t)row * 192 + c] = hi;
    ((uint2*)aggl)[(size_t)row * 192 + c] = lo;
}

__global__ __launch_bounds__(64) void gather_aggU(const float* __restrict__ huf,
                                                  __nv_bfloat16* __restrict__ aggh,
                                                  __nv_bfloat16* __restrict__ aggl,
                                                  int stride_u2, int off_u2) {
    int row = blockIdx.x;
    int c   = threadIdx.x;
    float4 acc = make_float4(0.f, 0.f, 0.f, 0.f);
    int e = g_offRD[row], e1 = g_offRD[row + 1];
    for (; e + 1 < e1; e += 2) {
        int s0 = g_ndRD[e], s1 = g_ndRD[e + 1];
        float n0 = g_nmRD[e], n1 = g_nmRD[e + 1];
        float4 v0 = ((const float4*)huf)[(size_t)s0 * 64 + c];
        float4 v1 = ((const float4*)huf)[(size_t)s1 * 64 + c];
        acc.x += v0.x * n0 + v1.x * n1; acc.y += v0.y * n0 + v1.y * n1;
        acc.z += v0.z * n0 + v1.z * n1; acc.w += v0.w * n0 + v1.w * n1;
    }
    if (e < e1) {
        int s0 = g_ndRD[e]; float n0 = g_nmRD[e];
        float4 v0 = ((const float4*)huf)[(size_t)s0 * 64 + c];
        acc.x += v0.x * n0; acc.y += v0.y * n0; acc.z += v0.z * n0; acc.w += v0.w * n0;
    }
    uint2 hi = split_pack(acc);
    uint2 lo = split_pack_lo(acc, hi);
    ((uint2*)aggh)[(size_t)row * stride_u2 + off_u2 + c] = hi;
    ((uint2*)aggl)[(size_t)row * stride_u2 + off_u2 + c] = lo;
}

__global__ __launch_bounds__(64) void gather_aggRR(const float* __restrict__ hrf,
                                                   __nv_bfloat16* __restrict__ aggh,
                                                   __nv_bfloat16* __restrict__ aggl,
                                                   int stride_u2, int off_u2) {
    int row = blockIdx.x;
    int c   = threadIdx.x;
    float coef = g_inv_ds[row] * g_inv_dd[row];
    float4 own = ((const float4*)hrf)[(size_t)row * 64 + c];
    float4 acc = make_float4(own.x * coef, own.y * coef, own.z * coef, own.w * coef);
    int e = g_offND[row], e1 = g_offND[row + 1];
    for (; e + 1 < e1; e += 2) {
        int s0 = g_ndND[e], s1 = g_ndND[e + 1];
        float n0 = g_nmND[e], n1 = g_nmND[e + 1];
        float4 v0 = ((const float4*)hrf)[(size_t)s0 * 64 + c];
        float4 v1 = ((const float4*)hrf)[(size_t)s1 * 64 + c];
        acc.x += v0.x * n0 + v1.x * n1; acc.y += v0.y * n0 + v1.y * n1;
        acc.z += v0.z * n0 + v1.z * n1; acc.w += v0.w * n0 + v1.w * n1;
    }
    if (e < e1) {
        int s0 = g_ndND[e]; float n0 = g_nmND[e];
        float4 v0 = ((const float4*)hrf)[(size_t)s0 * 64 + c];
        acc.x += v0.x * n0; acc.y += v0.y * n0; acc.z += v0.z * n0; acc.w += v0.w * n0;
    }
    uint2 hi = split_pack(acc);
    uint2 lo = split_pack_lo(acc, hi);
    ((uint2*)aggh)[(size_t)row * stride_u2 + off_u2 + c] = hi;
    ((uint2*)aggl)[(size_t)row * stride_u2 + off_u2 + c] = lo;
}

// user gather with row offset (for row-split pipelining)
__global__ __launch_bounds__(64) void gather_user(const float* __restrict__ tru,
                                                  const float* __restrict__ bru,
                                                  __nv_bfloat16* __restrict__ hh,
                                                  __nv_bfloat16* __restrict__ hl,
                                                  float* __restrict__ hf,
                                                  int row_base) {
    int row = row_base + blockIdx.x;
    int c   = threadIdx.x;
    float4 acc = ((const float4*)bru)[c];

    int e = g_offRS[row], e1 = g_offRS[row + 1];
    for (; e + 1 < e1; e += 2) {
        int s0 = g_ndRS[e], s1 = g_ndRS[e + 1];
        float n0 = g_nmRS[e], n1 = g_nmRS[e + 1];
        float4 v0 = ((const float4*)tru)[(size_t)s0 * 64 + c];
        float4 v1 = ((const float4*)tru)[(size_t)s1 * 64 + c];
        acc.x += v0.x * n0 + v1.x * n1; acc.y += v0.y * n0 + v1.y * n1;
        acc.z += v0.z * n0 + v1.z * n1; acc.w += v0.w * n0 + v1.w * n1;
    }
    if (e < e1) {
        int s0 = g_ndRS[e]; float n0 = g_nmRS[e];
        float4 v0 = ((const float4*)tru)[(size_t)s0 * 64 + c];
        acc.x += v0.x * n0; acc.y += v0.y * n0; acc.z += v0.z * n0; acc.w += v0.w * n0;
    }

    acc = make_float4(fmaxf(acc.x, 0.f), fmaxf(acc.y, 0.f),
                      fmaxf(acc.z, 0.f), fmaxf(acc.w, 0.f));
    if (hh) {
        uint2 hi = split_pack(acc);
        uint2 lo = split_pack_lo(acc, hi);
        ((uint2*)hh)[(size_t)row * 64 + c] = hi;
        ((uint2*)hl)[(size_t)row * 64 + c] = lo;
    }
    if (hf) ((float4*)hf)[(size_t)row * 64 + c] = acc;
}

// ---------------- host orchestration ----------------------------------------
extern "C" void kernel_launch(void* const* d_in, const int* in_sizes, int n_in,
                              void* d_out, int out_size) {
    const float* x_user    = (const float*)d_in[0];
    const float* x_rest    = (const float*)d_in[1];
    const int*   rev_src   = (const int*)d_in[2];
    const int*   rev_dst   = (const int*)d_in[3];
    const int*   near_src  = (const int*)d_in[4];
    const int*   near_dst  = (const int*)d_in[5];
    const float* Win_user  = (const float*)d_in[6];
    const float* Win_rest  = (const float*)d_in[7];
    const float* W1_ur = (const float*)d_in[8];
    const float* b1_ur = (const float*)d_in[9];
    const float* W1_ru = (const float*)d_in[10];
    const float* b1_ru = (const float*)d_in[11];
    const float* W1_rr = (const float*)d_in[12];
    const float* b1_rr = (const float*)d_in[13];
    const float* W2_ur = (const float*)d_in[14];
    const float* b2_ur = (const float*)d_in[15];
    const float* W2_ru = (const float*)d_in[16];
    const float* b2_ru = (const float*)d_in[17];
    const float* W2_rr = (const float*)d_in[18];
    const float* b2_rr = (const float*)d_in[19];
    const float* Wout_user = (const float*)d_in[20];
    const float* Wout_rest = (const float*)d_in[21];

    cudaFuncSetAttribute(wgemm2, cudaFuncAttributeMaxDynamicSharedMemorySize, GEMM_SMEM);

    static cudaStream_t s2 = nullptr;
    static cudaEvent_t evFork, evPR, evT1, evR1, evT2, evAG1, evAG2, evGUa, evJoin;
    if (!s2) {
        cudaStreamCreateWithFlags(&s2, cudaStreamNonBlocking);
        cudaEventCreateWithFlags(&evFork, cudaEventDisableTiming);
        cudaEventCreateWithFlags(&evPR,   cudaEventDisableTiming);
        cudaEventCreateWithFlags(&evT1,   cudaEventDisableTiming);
        cudaEventCreateWithFlags(&evR1,   cudaEventDisableTiming);
        cudaEventCreateWithFlags(&evT2,   cudaEventDisableTiming);
        cudaEventCreateWithFlags(&evAG1,  cudaEventDisableTiming);
        cudaEventCreateWithFlags(&evAG2,  cudaEventDisableTiming);
        cudaEventCreateWithFlags(&evGUa,  cudaEventDisableTiming);
        cudaEventCreateWithFlags(&evJoin, cudaEventDisableTiming);
    }

    float *tru1, *tru2, *huBf, *hrAf, *hrBf;
    float *inv_du, *inv_dr, *inv_ds, *inv_dd;
    int *deg, *offRD, *offND, *offRS, *curRD, *curND, *curRS, *ndRD, *ndND, *ndRS;
    float *nmRD, *nmND, *nmRS;
    __nv_bfloat16 *xrh, *xrl, *wh, *wl, *agg1h, *agg1l, *agg2h, *agg2l;
    __nv_bfloat16 *huAh, *huAl, *hrAh, *hrAl, *hrBh, *hrBl;
    cudaGetSymbolAddress((void**)&tru1, g_tru1);
    cudaGetSymbolAddress((void**)&tru2, g_tru2);
    cudaGetSymbolAddress((void**)&huBf, g_huBf);
    cudaGetSymbolAddress((void**)&hrAf, g_hrAf);
    cudaGetSymbolAddress((void**)&hrBf, g_hrBf);
    cudaGetSymbolAddress((void**)&inv_du, g_inv_du);
    cudaGetSymbolAddress((void**)&inv_dr, g_inv_dr);
    cudaGetSymbolAddress((void**)&inv_ds, g_inv_ds);
    cudaGetSymbolAddress((void**)&inv_dd, g_inv_dd);
    cudaGetSymbolAddress((void**)&deg, g_deg);
    cudaGetSymbolAddress((void**)&offRD, g_offRD);
    cudaGetSymbolAddress((void**)&offND, g_offND);
    cudaGetSymbolAddress((void**)&offRS, g_offRS);
    cudaGetSymbolAddress((void**)&curRD, g_curRD);
    cudaGetSymbolAddress((void**)&curND, g_curND);
    cudaGetSymbolAddress((void**)&curRS, g_curRS);
    cudaGetSymbolAddress((void**)&ndRD, g_ndRD);
    cudaGetSymbolAddress((void**)&ndND, g_ndND);
    cudaGetSymbolAddress((void**)&ndRS, g_ndRS);
    cudaGetSymbolAddress((void**)&nmRD, g_nmRD);
    cudaGetSymbolAddress((void**)&nmND, g_nmND);
    cudaGetSymbolAddress((void**)&nmRS, g_nmRS);
    cudaGetSymbolAddress((void**)&xrh, g_xrh);
    cudaGetSymbolAddress((void**)&xrl, g_xrl);
    cudaGetSymbolAddress((void**)&huAh, g_huAh);
    cudaGetSymbolAddress((void**)&huAl, g_huAl);
    cudaGetSymbolAddress((void**)&hrAh, g_hrAh);
    cudaGetSymbolAddress((void**)&hrAl, g_hrAl);
    cudaGetSymbolAddress((void**)&hrBh, g_hrBh);
    cudaGetSymbolAddress((void**)&hrBl, g_hrBl);
    cudaGetSymbolAddress((void**)&agg1h, g_agg1h);
    cudaGetSymbolAddress((void**)&agg1l, g_agg1l);
    cudaGetSymbolAddress((void**)&agg2h, g_agg2h);
    cudaGetSymbolAddress((void**)&agg2l, g_agg2l);
    cudaGetSymbolAddress((void**)&wh, g_wh);
    cudaGetSymbolAddress((void**)&wl, g_wl);

    int* du = deg;
    int* dr = deg + NU;
    int* ds = dr + NR;
    int* dd = ds + NR;

    const int O_WIN_U = 0;
    const int O_WIN_R = 131072;
    const int O_RU1   = 262144;
    const int O_RU2   = 327680;
    const int O_W1UR  = 393216;
    const int O_WCOMB = 458752;
    const int O_W1RR  = 589824;
    const int O_CAT2  = 655360;
    const int O_OUTU  = 786432;
    const int O_OUTR  = 851968;

    dim3 gR(1, CDIV(NR, BM));
    dim3 gW(1, CDIV(512, BM));
    dim3 gUa(1, CDIV(NU_H1, BM));
    dim3 gUb(1, CDIV(NU - NU_H1, BM));

    // ===== fork s2 =====
    cudaEventRecord(evFork, 0);
    cudaStreamWaitEvent(s2, evFork, 0);

    // ----- s2: weight/input splits, Wcomb, rest projection -----
    split_bf16<<<CDIV(DIN*H/4, 256), 256, 0, s2>>>(Win_user, wh + O_WIN_U, wl + O_WIN_U, DIN*H/4);
    split_bf16<<<CDIV(H*H/4, 256), 256, 0, s2>>>(W1_ur, wh + O_W1UR, wl + O_W1UR, H*H/4);
    split_bf16<<<CDIV(DIN*H/4, 256), 256, 0, s2>>>(Win_rest, wh + O_WIN_R, wl + O_WIN_R, DIN*H/4);
    split_bf16<<<CDIV(H*H/4, 256), 256, 0, s2>>>(W1_ru, wh + O_RU1, wl + O_RU1, H*H/4);
    split_bf16<<<CDIV(H*H/4, 256), 256, 0, s2>>>(W2_ru, wh + O_RU2, wl + O_RU2, H*H/4);
    split_bf16<<<CDIV(H*H/4, 256), 256, 0, s2>>>(W1_rr, wh + O_W1RR, wl + O_W1RR, H*H/4);
    split_bf16<<<CDIV(H*H/4, 256), 256, 0, s2>>>(W2_ur, wh + O_CAT2, wl + O_CAT2, H*H/4);
    split_bf16<<<CDIV(H*H/4, 256), 256, 0, s2>>>(W2_rr, wh + O_CAT2 + H*H, wl + O_CAT2 + H*H, H*H/4);
    split_bf16<<<CDIV(H*H/4, 256), 256, 0, s2>>>(Wout_user, wh + O_OUTU, wl + O_OUTU, H*H/4);
    split_bf16<<<CDIV(H*H/4, 256), 256, 0, s2>>>(Wout_rest, wh + O_OUTR, wl + O_OUTR, H*H/4);
    split_bf16<<<CDIV(NR*DIN/4, 256), 256, 0, s2>>>(x_rest, xrh, xrl, NR*DIN/4);
    wgemm2<<<gW, 256, GEMM_SMEM, s2>>>(wh + O_WIN_U, wl + O_WIN_U, wh + O_W1UR, wl + O_W1UR,
                                       nullptr, wh + O_WCOMB, wl + O_WCOMB, nullptr,
                                       nullptr, nullptr, 0, 512, 256);
    wgemm2<<<gR, 256, GEMM_SMEM, s2>>>(xrh, xrl, wh + O_WIN_R, wl + O_WIN_R,
                                       nullptr, hrAh, hrAl, hrAf,
                                       nullptr, nullptr, 0, NR, DIN);
    cudaEventRecord(evPR, s2);

    // ----- stream0: CSR build, then raw-input ur-gather -----
    cudaMemsetAsync(deg, 0, sizeof(int) * (NU + 3 * NR));
    count_deg<<<CDIV(EREV, 256), 256>>>(rev_src, du, EREV);
    count_deg<<<CDIV(EREV, 256), 256>>>(rev_dst, dr, EREV);
    count_deg<<<CDIV(ENEAR, 256), 256>>>(near_src, ds, ENEAR);
    count_deg<<<CDIV(ENEAR, 256), 256>>>(near_dst, dd, ENEAR);
    make_inv<<<CDIV(NU, 256), 256>>>(du, inv_du, NU, 0);
    make_inv<<<CDIV(NR, 256), 256>>>(dr, inv_dr, NR, 0);
    make_inv<<<CDIV(NR, 256), 256>>>(ds, inv_ds, NR, 1);
    make_inv<<<CDIV(NR, 256), 256>>>(dd, inv_dd, NR, 1);
    scan3<<<3, 1024>>>(dr, offRD, NR, dd, offND, NR, du, offRS, NU);
    cudaMemcpyAsync(curRD, offRD, sizeof(int) * NR, cudaMemcpyDeviceToDevice);
    cudaMemcpyAsync(curND, offND, sizeof(int) * NR, cudaMemcpyDeviceToDevice);
    cudaMemcpyAsync(curRS, offRS, sizeof(int) * NU, cudaMemcpyDeviceToDevice);
    fill_bucket<<<CDIV(EREV, 256), 256>>>(rev_dst, rev_src, inv_dr, inv_du, curRD, ndRD, nmRD, EREV);
    fill_bucket<<<CDIV(ENEAR, 256), 256>>>(near_dst, near_src, inv_dd, inv_ds, curND, ndND, nmND, ENEAR);
    fill_bucket<<<CDIV(EREV, 256), 256>>>(rev_src, rev_dst, inv_du, inv_dr, curRS, ndRS, nmRS, EREV);

    gather_aggX<<<NR, 128>>>(x_user, agg1h, agg1l);
    cudaStreamWaitEvent(0, evPR, 0);
    gather_aggRR<<<NR, 64>>>(hrAf, agg1h, agg1l, 192, 128);
    cudaEventRecord(evAG1, 0);

    // ----- s2: layer 1 GEMMs -----
    wgemm2<<<gR, 256, GEMM_SMEM, s2>>>(hrAh, hrAl, wh + O_RU1, wl + O_RU1,
                                       tru1, nullptr, nullptr, nullptr,
                                       nullptr, nullptr, 0, NR, H);
    cudaEventRecord(evT1, s2);
    cudaStreamWaitEvent(s2, evAG1, 0);
    wgemm2<<<gR, 256, GEMM_SMEM, s2>>>(agg1h, agg1l, wh + O_WCOMB, wl + O_WCOMB,
                                       nullptr, hrBh, hrBl, hrBf,
                                       b1_ur, b1_rr, 1, NR, 768);
    cudaEventRecord(evR1, s2);
    wgemm2<<<gR, 256, GEMM_SMEM, s2>>>(hrBh, hrBl, wh + O_RU2, wl + O_RU2,
                                       tru2, nullptr, nullptr, nullptr,
                                       nullptr, nullptr, 0, NR, H);
    cudaEventRecord(evT2, s2);

    // ----- stream0: user gather L1, agg gathers L2 -----
    cudaStreamWaitEvent(0, evT1, 0);
    gather_user<<<NU, 64>>>(tru1, b1_ru, nullptr, nullptr, huBf, 0);
    cudaStreamWaitEvent(0, evR1, 0);
    gather_aggRR<<<NR, 64>>>(hrBf, agg2h, agg2l, 128, 64);
    gather_aggU<<<NR, 64>>>(huBf, agg2h, agg2l, 128, 0);
    cudaEventRecord(evAG2, 0);

    // ----- s2: layer 2 CAT GEMM + rest output -----
    cudaStreamWaitEvent(s2, evAG2, 0);
    wgemm2<<<gR, 256, GEMM_SMEM, s2>>>(agg2h, agg2l, wh + O_CAT2, wl + O_CAT2,
                                       nullptr, hrAh, hrAl, nullptr,
                                       b2_ur, b2_rr, 1, NR, 2 * H);
    float* out = (float*)d_out;
    wgemm2<<<gR, 256, GEMM_SMEM, s2>>>(hrAh, hrAl, wh + O_OUTR, wl + O_OUTR,
                                       out + (size_t)NU * H, nullptr, nullptr, nullptr,
                                       nullptr, nullptr, 0, NR, H);

    // ----- tail: row-split gather/GEMM pipeline -----
    // stream0: gather rows [0, NU_H1) -> evGUa -> gather rows [NU_H1, NU) -> outU half B
    cudaStreamWaitEvent(0, evT2, 0);
    gather_user<<<NU_H1, 64>>>(tru2, b2_ru, huAh, huAl, nullptr, 0);
    cudaEventRecord(evGUa, 0);
    gather_user<<<NU - NU_H1, 64>>>(tru2, b2_ru, huAh, huAl, nullptr, NU_H1);
    wgemm2<<<gUb, 256, GEMM_SMEM>>>(huAh + (size_t)NU_H1 * H, huAl + (size_t)NU_H1 * H,
                                    wh + O_OUTU, wl + O_OUTU,
                                    out + (size_t)NU_H1 * H, nullptr, nullptr, nullptr,
                                    nullptr, nullptr, 0, NU - NU_H1, H);
    // s2: after outR, overlap outU half A with stream0's gather half B
    cudaStreamWaitEvent(s2, evGUa, 0);
    wgemm2<<<gUa, 256, GEMM_SMEM, s2>>>(huAh, huAl, wh + O_OUTU, wl + O_OUTU,
                                        out, nullptr, nullptr, nullptr,
                                        nullptr, nullptr, 0, NU_H1, H);
    cudaEventRecord(evJoin, s2);
    cudaStreamWaitEvent(0, evJoin, 0);
}

// round 15
// speedup vs baseline: 1.0298x; 1.0246x over previous
#include <cuda_runtime.h>
#include <cuda_bf16.h>
#include <mma.h>
#include <cstddef>
#include <cstdint>

using namespace nvcuda;

#define CDIV(a,b) (((a)+(b)-1)/(b))

constexpr int NU    = 50000;
constexpr int NR    = 20000;
constexpr int DIN   = 512;
constexpr int H     = 256;
constexpr int EREV  = 500000;
constexpr int ENEAR = 250000;

// ---------------- scratch (static device globals; no allocations) ----------
__device__ float g_tru1[(size_t)NR * H];
__device__ float g_tru2[(size_t)NR * H];
__device__ float g_huBf[(size_t)NU * H];
__device__ float g_hrAf[(size_t)NR * H];
__device__ float g_hrBf[(size_t)NR * H];
__device__ int   g_deg[NU + 3 * NR];
__device__ float g_inv_du[NU];
__device__ float g_inv_dr[NR];
__device__ float g_inv_ds[NR];
__device__ float g_inv_dd[NR];
// CSR buckets
__device__ int   g_offRD[NR + 1], g_offND[NR + 1], g_offRS[NU + 1];
__device__ int   g_curRD[NR],     g_curND[NR],     g_curRS[NU];
__device__ int   g_ndRD[EREV],   g_ndND[ENEAR],   g_ndRS[EREV];
__device__ float g_nmRD[EREV],   g_nmND[ENEAR],   g_nmRS[EREV];
// bf16 hi/lo GEMM operands
__device__ __nv_bfloat16 g_xrh[(size_t)NR * DIN], g_xrl[(size_t)NR * DIN];
__device__ __nv_bfloat16 g_huAh[(size_t)NU * H], g_huAl[(size_t)NU * H];
__device__ __nv_bfloat16 g_hrAh[(size_t)NR * H], g_hrAl[(size_t)NR * H];
__device__ __nv_bfloat16 g_hrBh[(size_t)NR * H], g_hrBl[(size_t)NR * H];
__device__ __nv_bfloat16 g_agg1h[(size_t)NR * 768], g_agg1l[(size_t)NR * 768];
__device__ __nv_bfloat16 g_agg2h[(size_t)NR * 512], g_agg2l[(size_t)NR * 512];
constexpr int WTOT = 917504;
__device__ __nv_bfloat16 g_wh[WTOT], g_wl[WTOT];

// ---------------- helpers ----------------------------------------------------
__device__ __forceinline__ uint32_t smem_u32(const void* p) {
    uint32_t a;
    asm("{ .reg .u64 t; cvta.to.shared.u64 t, %1; cvt.u32.u64 %0, t; }" : "=r"(a) : "l"(p));
    return a;
}
__device__ __forceinline__ void cp16(uint32_t dst, const void* src, bool ok) {
    int sz = ok ? 16 : 0;
    asm volatile("cp.async.cg.shared.global [%0], [%1], 16, %2;"
                 :: "r"(dst), "l"(src), "r"(sz) : "memory");
}
#define CP_COMMIT() asm volatile("cp.async.commit_group;" ::: "memory")
#define CP_WAIT2()  asm volatile("cp.async.wait_group 2;" ::: "memory")

__device__ __forceinline__ uint2 split_pack(float4 v) {
    __nv_bfloat16 h0 = __float2bfloat16_rn(v.x), h1 = __float2bfloat16_rn(v.y);
    __nv_bfloat16 h2 = __float2bfloat16_rn(v.z), h3 = __float2bfloat16_rn(v.w);
    __nv_bfloat162 a = __halves2bfloat162(h0, h1);
    __nv_bfloat162 b = __halves2bfloat162(h2, h3);
    uint2 r;
    r.x = *(uint32_t*)&a; r.y = *(uint32_t*)&b;
    return r;
}
__device__ __forceinline__ uint2 split_pack_lo(float4 v, uint2 hi) {
    __nv_bfloat162 a = *(__nv_bfloat162*)&hi.x;
    __nv_bfloat162 b = *(__nv_bfloat162*)&hi.y;
    float4 r = make_float4(v.x - __bfloat162float(__low2bfloat16(a)),
                           v.y - __bfloat162float(__high2bfloat16(a)),
                           v.z - __bfloat162float(__low2bfloat16(b)),
                           v.w - __bfloat162float(__high2bfloat16(b)));
    return split_pack(r);
}

// ---------------- split kernel ------------------------------------------------
__global__ void split_bf16(const float* __restrict__ in,
                           __nv_bfloat16* __restrict__ h,
                           __nv_bfloat16* __restrict__ l, int n4) {
    int i = blockIdx.x * 256 + threadIdx.x;
    if (i >= n4) return;
    float4 v = ((const float4*)in)[i];
    uint2 hi = split_pack(v);
    uint2 lo = split_pack_lo(v, hi);
    ((uint2*)h)[i] = hi;
    ((uint2*)l)[i] = lo;
}

// ---------------- 3-stage-pipelined bf16-split wmma GEMM --------------------
// Block tile 128 x 256 (full N), 8 warps = 2x4 of 64x64 warp tiles, BK=32.
constexpr int BM = 128, BN = 256, BK = 32;
constexpr int LDA = BK + 8;
constexpr int LDB = BN + 8;
constexpr int E_AH = 0;
constexpr int E_AL = E_AH + BM * LDA;
constexpr int E_BH = E_AL + BM * LDA;
constexpr int E_BL = E_BH + BK * LDB;
constexpr int STAGE_E = E_BL + BK * LDB;       // 27136 elems = 54272 B
constexpr int GEMM_SMEM = 3 * STAGE_E * 2;     // 162816 B

__global__ __launch_bounds__(256, 1) void wgemm2(const __nv_bfloat16* __restrict__ Ahg,
                                                 const __nv_bfloat16* __restrict__ Alg,
                                                 const __nv_bfloat16* __restrict__ Bhg,
                                                 const __nv_bfloat16* __restrict__ Blg,
                                                 float* __restrict__ C,
                                                 __nv_bfloat16* __restrict__ Ch,
                                                 __nv_bfloat16* __restrict__ Cl,
                                                 float* __restrict__ Cf,
                                                 const float* __restrict__ bias0,
                                                 const float* __restrict__ bias1,
                                                 int do_relu,
                                                 int M, int K) {
    extern __shared__ __nv_bfloat16 sm[];
    uint32_t sbase = smem_u32(sm);

    int tid  = threadIdx.x;
    int wid  = tid >> 5;
    int lane = tid & 31;
    int row0 = blockIdx.y * BM;
    int wm   = wid >> 2;
    int wn   = wid & 3;

    wmma::fragment<wmma::accumulator, 16, 16, 16, float> acc[4][4];
#pragma unroll
    for (int mi = 0; mi < 4; mi++)
#pragma unroll
        for (int ni = 0; ni < 4; ni++) wmma::fill_fragment(acc[mi][ni], 0.f);

    auto load_stage = [&](int st, int k0) {
        uint32_t base = sbase + st * (STAGE_E * 2);
#pragma unroll
        for (int q = 0; q < 2; q++) {
            int i   = tid + 256 * q;
            int row = i >> 2;
            int c8  = (i & 3) << 3;
            bool ok = (row0 + row) < M;
            size_t off = (size_t)(ok ? row0 + row : 0) * K + k0 + c8;
            uint32_t d = base + (row * LDA + c8) * 2;
            cp16(d, Ahg + off, ok);
            cp16(d + E_AL * 2, Alg + off, ok);
        }
#pragma unroll
        for (int q = 0; q < 4; q++) {
            int i  = tid + 256 * q;
            int kk = i >> 5;
            int c8 = (i & 31) << 3;
            size_t off = (size_t)(k0 + kk) * 256 + c8;
            uint32_t d = base + E_BH * 2 + (kk * LDB + c8) * 2;
            cp16(d, Bhg + off, true);
            cp16(d + (E_BL - E_BH) * 2, Blg + off, true);
        }
    };

    int NC = K / BK;
    load_stage(0, 0);
    CP_COMMIT();
    if (NC > 1) load_stage(1, BK);
    CP_COMMIT();

    for (int c = 0; c < NC; c++) {
        if (c + 2 < NC) load_stage((c + 2) % 3, (c + 2) * BK);
        CP_COMMIT();                 // empty groups at tail keep the count aligned
        CP_WAIT2();                  // group for iteration c is complete
        __syncthreads();

        const __nv_bfloat16* sAh = sm + (c % 3) * STAGE_E + E_AH;
        const __nv_bfloat16* sAl = sm + (c % 3) * STAGE_E + E_AL;
        const __nv_bfloat16* sBh = sm + (c % 3) * STAGE_E + E_BH;
        const __nv_bfloat16* sBl = sm + (c % 3) * STAGE_E + E_BL;

#pragma unroll
        for (int kk = 0; kk < BK; kk += 16) {
            wmma::fragment<wmma::matrix_a, 16, 16, 16, __nv_bfloat16, wmma::row_major> ah[4], al[4];
#pragma unroll
            for (int mi = 0; mi < 4; mi++) {
                wmma::load_matrix_sync(ah[mi], sAh + (wm * 64 + mi * 16) * LDA + kk, LDA);
                wmma::load_matrix_sync(al[mi], sAl + (wm * 64 + mi * 16) * LDA + kk, LDA);
            }
#pragma unroll
            for (int ni = 0; ni < 4; ni++) {
                wmma::fragment<wmma::matrix_b, 16, 16, 16, __nv_bfloat16, wmma::row_major> bh, bl;
                wmma::load_matrix_sync(bh, sBh + kk * LDB + wn * 64 + ni * 16, LDB);
                wmma::load_matrix_sync(bl, sBl + kk * LDB + wn * 64 + ni * 16, LDB);
#pragma unroll
                for (int mi = 0; mi < 4; mi++) {
                    wmma::mma_sync(acc[mi][ni], ah[mi], bh, acc[mi][ni]);
                    wmma::mma_sync(acc[mi][ni], al[mi], bh, acc[mi][ni]);
                    wmma::mma_sync(acc[mi][ni], ah[mi], bl, acc[mi][ni]);
                }
            }
        }
        __syncthreads();
    }

    if (Ch != nullptr) {
        float* stage = (float*)sm + wid * 512;
#pragma unroll
        for (int mi = 0; mi < 4; mi++)
#pragma unroll
            for (int ni = 0; ni < 4; ni++) {
                wmma::store_matrix_sync(stage, acc[mi][ni], 20, wmma::mem_row_major);
                __syncwarp();
#pragma unroll
                for (int jj = 0; jj < 4; jj++) {
                    int e2 = lane * 4 + jj;
                    int r  = e2 >> 3;
                    int c0 = (e2 & 7) * 2;
                    int row = row0 + wm * 64 + mi * 16 + r;
                    if (row < M) {
                        int col = wn * 64 + ni * 16 + c0;
                        float v0 = stage[r * 20 + c0], v1 = stage[r * 20 + c0 + 1];
                        if (bias0) { v0 += bias0[col]; v1 += bias0[col + 1]; }
                        if (bias1) { v0 += bias1[col]; v1 += bias1[col + 1]; }
                        if (do_relu) { v0 = fmaxf(v0, 0.f); v1 = fmaxf(v1, 0.f); }
                        __nv_bfloat16 h0 = __float2bfloat16_rn(v0);
                        __nv_bfloat16 h1 = __float2bfloat16_rn(v1);
                        __nv_bfloat16 l0 = __float2bfloat16_rn(v0 - __bfloat162float(h0));
                        __nv_bfloat16 l1 = __float2bfloat16_rn(v1 - __bfloat162float(h1));
                        size_t off = (size_t)row * 256 + col;
                        *(__nv_bfloat162*)(Ch + off) = __halves2bfloat162(h0, h1);
                        *(__nv_bfloat162*)(Cl + off) = __halves2bfloat162(l0, l1);
                        if (Cf) { Cf[off] = v0; Cf[off + 1] = v1; }
                    }
                }
                __syncwarp();
            }
    } else if (row0 + BM <= M) {
#pragma unroll
        for (int mi = 0; mi < 4; mi++)
#pragma unroll
            for (int ni = 0; ni < 4; ni++) {
                float* cp = C + (size_t)(row0 + wm * 64 + mi * 16) * 256
                              + wn * 64 + ni * 16;
                wmma::store_matrix_sync(cp, acc[mi][ni], 256, wmma::mem_row_major);
            }
    } else {
        float* stage = (float*)sm + wid * 512;
#pragma unroll
        for (int mi = 0; mi < 4; mi++)
#pragma unroll
            for (int ni = 0; ni < 4; ni++) {
                wmma::store_matrix_sync(stage, acc[mi][ni], 20, wmma::mem_row_major);
                __syncwarp();
#pragma unroll
                for (int j = 0; j < 8; j++) {
                    int e   = lane * 8 + j;
                    int r   = e >> 4, cc = e & 15;
                    int row = row0 + wm * 64 + mi * 16 + r;
                    if (row < M)
                        C[(size_t)row * 256 + wn * 64 + ni * 16 + cc] =
                            stage[r * 20 + cc];
                }
                __syncwarp();
            }
    }
}

// ---------------- CSR build kernels -----------------------------------------
__global__ void count_deg(const int* __restrict__ idx, int* __restrict__ deg, int E) {
    int i = blockIdx.x * 256 + threadIdx.x;
    if (i < E) atomicAdd(&deg[idx[i]], 1);
}

__global__ void make_inv(const int* __restrict__ deg, float* __restrict__ inv, int n, int add) {
    int i = blockIdx.x * 256 + threadIdx.x;
    if (i < n) {
        int d = deg[i] + add;
        inv[i] = d > 0 ? rsqrtf((float)d) : 0.f;
    }
}

__global__ __launch_bounds__(1024) void scan3(const int* c0, int* o0, int n0,
                                              const int* c1, int* o1, int n1,
                                              const int* c2, int* o2, int n2) {
    const int* cnt = blockIdx.x == 0 ? c0 : blockIdx.x == 1 ? c1 : c2;
    int* off = blockIdx.x == 0 ? o0 : blockIdx.x == 1 ? o1 : o2;
    int n    = blockIdx.x == 0 ? n0 : blockIdx.x == 1 ? n1 : n2;
    __shared__ int tmp[1024];
    __shared__ int carry;
    if (threadIdx.x == 0) carry = 0;
    __syncthreads();
    for (int base = 0; base < n; base += 1024) {
        int i = base + (int)threadIdx.x;
        int v = (i < n) ? cnt[i] : 0;
        tmp[threadIdx.x] = v;
        __syncthreads();
#pragma unroll
        for (int s = 1; s < 1024; s <<= 1) {
            int t = (threadIdx.x >= (unsigned)s) ? tmp[threadIdx.x - s] : 0;
            __syncthreads();
            tmp[threadIdx.x] += t;
            __syncthreads();
        }
        if (i < n) off[i] = carry + tmp[threadIdx.x] - v;
        __syncthreads();
        if (threadIdx.x == 0) carry += tmp[1023];
        __syncthreads();
    }
    if (threadIdx.x == 0) off[n] = carry;
}

__global__ void fill_bucket(const int* __restrict__ key, const int* __restrict__ other,
                            const float* __restrict__ inv_k, const float* __restrict__ inv_o,
                            int* __restrict__ cursor,
                            int* __restrict__ nodes, float* __restrict__ norms, int E) {
    int i = blockIdx.x * 256 + threadIdx.x;
    if (i >= E) return;
    int k = key[i], o = other[i];
    int pos = atomicAdd(&cursor[k], 1);
    nodes[pos] = o;
    norms[pos] = inv_k[k] * inv_o[o];
}

// ---------------- gathers -----------------------------------------------------
__global__ __launch_bounds__(128) void gather_aggX(const float* __restrict__ xu,
                                                   __nv_bfloat16* __restrict__ aggh,
                                                   __nv_bfloat16* __restrict__ aggl) {
    int row = blockIdx.x;
    int c   = threadIdx.x;
    float4 acc = make_float4(0.f, 0.f, 0.f, 0.f);
    int e = g_offRD[row], e1 = g_offRD[row + 1];
    for (; e < e1; e++) {
        int s = g_ndRD[e];
        float n = g_nmRD[e];
        float4 v = ((const float4*)xu)[(size_t)s * 128 + c];
        acc.x += v.x * n; acc.y += v.y * n; acc.z += v.z * n; acc.w += v.w * n;
    }
    uint2 hi = split_pack(acc);
    uint2 lo = split_pack_lo(acc, hi);
    ((uint2*)aggh)[(size_t)row * 192 + c] = hi;
    ((uint2*)aggl)[(size_t)row * 192 + c] = lo;
}

__global__ __launch_bounds__(64) void gather_aggU(const float* __restrict__ huf,
                                                  __nv_bfloat16* __restrict__ aggh,
                                                  __nv_bfloat16* __restrict__ aggl,
                                                  int stride_u2, int off_u2) {
    int row = blockIdx.x;
    int c   = threadIdx.x;
    float4 acc = make_float4(0.f, 0.f, 0.f, 0.f);
    int e = g_offRD[row], e1 = g_offRD[row + 1];
    for (; e + 1 < e1; e += 2) {
        int s0 = g_ndRD[e], s1 = g_ndRD[e + 1];
        float n0 = g_nmRD[e], n1 = g_nmRD[e + 1];
        float4 v0 = ((const float4*)huf)[(size_t)s0 * 64 + c];
        float4 v1 = ((const float4*)huf)[(size_t)s1 * 64 + c];
        acc.x += v0.x * n0 + v1.x * n1; acc.y += v0.y * n0 + v1.y * n1;
        acc.z += v0.z * n0 + v1.z * n1; acc.w += v0.w * n0 + v1.w * n1;
    }
    if (e < e1) {
        int s0 = g_ndRD[e]; float n0 = g_nmRD[e];
        float4 v0 = ((const float4*)huf)[(size_t)s0 * 64 + c];
        acc.x += v0.x * n0; acc.y += v0.y * n0; acc.z += v0.z * n0; acc.w += v0.w * n0;
    }
    uint2 hi = split_pack(acc);
    uint2 lo = split_pack_lo(acc, hi);
    ((uint2*)aggh)[(size_t)row * stride_u2 + off_u2 + c] = hi;
    ((uint2*)aggl)[(size_t)row * stride_u2 + off_u2 + c] = lo;
}

__global__ __launch_bounds__(64) void gather_aggRR(const float* __restrict__ hrf,
                                                   __nv_bfloat16* __restrict__ aggh,
                                                   __nv_bfloat16* __restrict__ aggl,
                                                   int stride_u2, int off_u2) {
    int row = blockIdx.x;
    int c   = threadIdx.x;
    float coef = g_inv_ds[row] * g_inv_dd[row];
    float4 own = ((const float4*)hrf)[(size_t)row * 64 + c];
    float4 acc = make_float4(own.x * coef, own.y * coef, own.z * coef, own.w * coef);
    int e = g_offND[row], e1 = g_offND[row + 1];
    for (; e + 1 < e1; e += 2) {
        int s0 = g_ndND[e], s1 = g_ndND[e + 1];
        float n0 = g_nmND[e], n1 = g_nmND[e + 1];
        float4 v0 = ((const float4*)hrf)[(size_t)s0 * 64 + c];
        float4 v1 = ((const float4*)hrf)[(size_t)s1 * 64 + c];
        acc.x += v0.x * n0 + v1.x * n1; acc.y += v0.y * n0 + v1.y * n1;
        acc.z += v0.z * n0 + v1.z * n1; acc.w += v0.w * n0 + v1.w * n1;
    }
    if (e < e1) {
        int s0 = g_ndND[e]; float n0 = g_nmND[e];
        float4 v0 = ((const float4*)hrf)[(size_t)s0 * 64 + c];
        acc.x += v0.x * n0; acc.y += v0.y * n0; acc.z += v0.z * n0; acc.w += v0.w * n0;
    }
    uint2 hi = split_pack(acc);
    uint2 lo = split_pack_lo(acc, hi);
    ((uint2*)aggh)[(size_t)row * stride_u2 + off_u2 + c] = hi;
    ((uint2*)aggl)[(size_t)row * stride_u2 + off_u2 + c] = lo;
}

__global__ __launch_bounds__(64) void gather_user(const float* __restrict__ tru,
                                                  const float* __restrict__ bru,
                                                  __nv_bfloat16* __restrict__ hh,
                                                  __nv_bfloat16* __restrict__ hl,
                                                  float* __restrict__ hf) {
    int row = blockIdx.x;
    int c   = threadIdx.x;
    float4 acc = ((const float4*)bru)[c];

    int e = g_offRS[row], e1 = g_offRS[row + 1];
    for (; e + 1 < e1; e += 2) {
        int s0 = g_ndRS[e], s1 = g_ndRS[e + 1];
        float n0 = g_nmRS[e], n1 = g_nmRS[e + 1];
        float4 v0 = ((const float4*)tru)[(size_t)s0 * 64 + c];
        float4 v1 = ((const float4*)tru)[(size_t)s1 * 64 + c];
        acc.x += v0.x * n0 + v1.x * n1; acc.y += v0.y * n0 + v1.y * n1;
        acc.z += v0.z * n0 + v1.z * n1; acc.w += v0.w * n0 + v1.w * n1;
    }
    if (e < e1) {
        int s0 = g_ndRS[e]; float n0 = g_nmRS[e];
        float4 v0 = ((const float4*)tru)[(size_t)s0 * 64 + c];
        acc.x += v0.x * n0; acc.y += v0.y * n0; acc.z += v0.z * n0; acc.w += v0.w * n0;
    }

    acc = make_float4(fmaxf(acc.x, 0.f), fmaxf(acc.y, 0.f),
                      fmaxf(acc.z, 0.f), fmaxf(acc.w, 0.f));
    if (hh) {
        uint2 hi = split_pack(acc);
        uint2 lo = split_pack_lo(acc, hi);
        ((uint2*)hh)[(size_t)row * 64 + c] = hi;
        ((uint2*)hl)[(size_t)row * 64 + c] = lo;
    }
    if (hf) ((float4*)hf)[(size_t)row * 64 + c] = acc;
}

// ---------------- host orchestration ----------------------------------------
extern "C" void kernel_launch(void* const* d_in, const int* in_sizes, int n_in,
                              void* d_out, int out_size) {
    const float* x_user    = (const float*)d_in[0];
    const float* x_rest    = (const float*)d_in[1];
    const int*   rev_src   = (const int*)d_in[2];
    const int*   rev_dst   = (const int*)d_in[3];
    const int*   near_src  = (const int*)d_in[4];
    const int*   near_dst  = (const int*)d_in[5];
    const float* Win_user  = (const float*)d_in[6];
    const float* Win_rest  = (const float*)d_in[7];
    const float* W1_ur = (const float*)d_in[8];
    const float* b1_ur = (const float*)d_in[9];
    const float* W1_ru = (const float*)d_in[10];
    const float* b1_ru = (const float*)d_in[11];
    const float* W1_rr = (const float*)d_in[12];
    const float* b1_rr = (const float*)d_in[13];
    const float* W2_ur = (const float*)d_in[14];
    const float* b2_ur = (const float*)d_in[15];
    const float* W2_ru = (const float*)d_in[16];
    const float* b2_ru = (const float*)d_in[17];
    const float* W2_rr = (const float*)d_in[18];
    const float* b2_rr = (const float*)d_in[19];
    const float* Wout_user = (const float*)d_in[20];
    const float* Wout_rest = (const float*)d_in[21];

    cudaFuncSetAttribute(wgemm2, cudaFuncAttributeMaxDynamicSharedMemorySize, GEMM_SMEM);

    static cudaStream_t s2 = nullptr;
    static cudaEvent_t evFork, evPR, evT1, evR1, evT2, evAG1, evAG2, evJoin;
    if (!s2) {
        cudaStreamCreateWithFlags(&s2, cudaStreamNonBlocking);
        cudaEventCreateWithFlags(&evFork, cudaEventDisableTiming);
        cudaEventCreateWithFlags(&evPR,   cudaEventDisableTiming);
        cudaEventCreateWithFlags(&evT1,   cudaEventDisableTiming);
        cudaEventCreateWithFlags(&evR1,   cudaEventDisableTiming);
        cudaEventCreateWithFlags(&evT2,   cudaEventDisableTiming);
        cudaEventCreateWithFlags(&evAG1,  cudaEventDisableTiming);
        cudaEventCreateWithFlags(&evAG2,  cudaEventDisableTiming);
        cudaEventCreateWithFlags(&evJoin, cudaEventDisableTiming);
    }

    float *tru1, *tru2, *huBf, *hrAf, *hrBf;
    float *inv_du, *inv_dr, *inv_ds, *inv_dd;
    int *deg, *offRD, *offND, *offRS, *curRD, *curND, *curRS, *ndRD, *ndND, *ndRS;
    float *nmRD, *nmND, *nmRS;
    __nv_bfloat16 *xrh, *xrl, *wh, *wl, *agg1h, *agg1l, *agg2h, *agg2l;
    __nv_bfloat16 *huAh, *huAl, *hrAh, *hrAl, *hrBh, *hrBl;
    cudaGetSymbolAddress((void**)&tru1, g_tru1);
    cudaGetSymbolAddress((void**)&tru2, g_tru2);
    cudaGetSymbolAddress((void**)&huBf, g_huBf);
    cudaGetSymbolAddress((void**)&hrAf, g_hrAf);
    cudaGetSymbolAddress((void**)&hrBf, g_hrBf);
    cudaGetSymbolAddress((void**)&inv_du, g_inv_du);
    cudaGetSymbolAddress((void**)&inv_dr, g_inv_dr);
    cudaGetSymbolAddress((void**)&inv_ds, g_inv_ds);
    cudaGetSymbolAddress((void**)&inv_dd, g_inv_dd);
    cudaGetSymbolAddress((void**)&deg, g_deg);
    cudaGetSymbolAddress((void**)&offRD, g_offRD);
    cudaGetSymbolAddress((void**)&offND, g_offND);
    cudaGetSymbolAddress((void**)&offRS, g_offRS);
    cudaGetSymbolAddress((void**)&curRD, g_curRD);
    cudaGetSymbolAddress((void**)&curND, g_curND);
    cudaGetSymbolAddress((void**)&curRS, g_curRS);
    cudaGetSymbolAddress((void**)&ndRD, g_ndRD);
    cudaGetSymbolAddress((void**)&ndND, g_ndND);
    cudaGetSymbolAddress((void**)&ndRS, g_ndRS);
    cudaGetSymbolAddress((void**)&nmRD, g_nmRD);
    cudaGetSymbolAddress((void**)&nmND, g_nmND);
    cudaGetSymbolAddress((void**)&nmRS, g_nmRS);
    cudaGetSymbolAddress((void**)&xrh, g_xrh);
    cudaGetSymbolAddress((void**)&xrl, g_xrl);
    cudaGetSymbolAddress((void**)&huAh, g_huAh);
    cudaGetSymbolAddress((void**)&huAl, g_huAl);
    cudaGetSymbolAddress((void**)&hrAh, g_hrAh);
    cudaGetSymbolAddress((void**)&hrAl, g_hrAl);
    cudaGetSymbolAddress((void**)&hrBh, g_hrBh);
    cudaGetSymbolAddress((void**)&hrBl, g_hrBl);
    cudaGetSymbolAddress((void**)&agg1h, g_agg1h);
    cudaGetSymbolAddress((void**)&agg1l, g_agg1l);
    cudaGetSymbolAddress((void**)&agg2h, g_agg2h);
    cudaGetSymbolAddress((void**)&agg2l, g_agg2l);
    cudaGetSymbolAddress((void**)&wh, g_wh);
    cudaGetSymbolAddress((void**)&wl, g_wl);

    int* du = deg;
    int* dr = deg + NU;
    int* ds = dr + NR;
    int* dd = ds + NR;

    const int O_WIN_U = 0;
    const int O_WIN_R = 131072;
    const int O_RU1   = 262144;
    const int O_RU2   = 327680;
    const int O_W1UR  = 393216;
    const int O_WCOMB = 458752;
    const int O_W1RR  = 589824;
    const int O_CAT2  = 655360;
    const int O_OUTU  = 786432;
    const int O_OUTR  = 851968;

    dim3 gU(1, CDIV(NU, BM));
    dim3 gR(1, CDIV(NR, BM));
    dim3 gW(1, CDIV(512, BM));

    // ===== fork s2 =====
    cudaEventRecord(evFork, 0);
    cudaStreamWaitEvent(s2, evFork, 0);

    // ----- s2: weight/input splits, Wcomb, rest projection -----
    split_bf16<<<CDIV(DIN*H/4, 256), 256, 0, s2>>>(Win_user, wh + O_WIN_U, wl + O_WIN_U, DIN*H/4);
    split_bf16<<<CDIV(H*H/4, 256), 256, 0, s2>>>(W1_ur, wh + O_W1UR, wl + O_W1UR, H*H/4);
    split_bf16<<<CDIV(DIN*H/4, 256), 256, 0, s2>>>(Win_rest, wh + O_WIN_R, wl + O_WIN_R, DIN*H/4);
    split_bf16<<<CDIV(H*H/4, 256), 256, 0, s2>>>(W1_ru, wh + O_RU1, wl + O_RU1, H*H/4);
    split_bf16<<<CDIV(H*H/4, 256), 256, 0, s2>>>(W2_ru, wh + O_RU2, wl + O_RU2, H*H/4);
    split_bf16<<<CDIV(H*H/4, 256), 256, 0, s2>>>(W1_rr, wh + O_W1RR, wl + O_W1RR, H*H/4);
    split_bf16<<<CDIV(H*H/4, 256), 256, 0, s2>>>(W2_ur, wh + O_CAT2, wl + O_CAT2, H*H/4);
    split_bf16<<<CDIV(H*H/4, 256), 256, 0, s2>>>(W2_rr, wh + O_CAT2 + H*H, wl + O_CAT2 + H*H, H*H/4);
    split_bf16<<<CDIV(H*H/4, 256), 256, 0, s2>>>(Wout_user, wh + O_OUTU, wl + O_OUTU, H*H/4);
    split_bf16<<<CDIV(H*H/4, 256), 256, 0, s2>>>(Wout_rest, wh + O_OUTR, wl + O_OUTR, H*H/4);
    split_bf16<<<CDIV(NR*DIN/4, 256), 256, 0, s2>>>(x_rest, xrh, xrl, NR*DIN/4);
    wgemm2<<<gW, 256, GEMM_SMEM, s2>>>(wh + O_WIN_U, wl + O_WIN_U, wh + O_W1UR, wl + O_W1UR,
                                       nullptr, wh + O_WCOMB, wl + O_WCOMB, nullptr,
                                       nullptr, nullptr, 0, 512, 256);
    wgemm2<<<gR, 256, GEMM_SMEM, s2>>>(xrh, xrl, wh + O_WIN_R, wl + O_WIN_R,
                                       nullptr, hrAh, hrAl, hrAf,
                                       nullptr, nullptr, 0, NR, DIN);
    cudaEventRecord(evPR, s2);

    // ----- stream0: CSR build, then raw-input ur-gather -----
    cudaMemsetAsync(deg, 0, sizeof(int) * (NU + 3 * NR));
    count_deg<<<CDIV(EREV, 256), 256>>>(rev_src, du, EREV);
    count_deg<<<CDIV(EREV, 256), 256>>>(rev_dst, dr, EREV);
    count_deg<<<CDIV(ENEAR, 256), 256>>>(near_src, ds, ENEAR);
    count_deg<<<CDIV(ENEAR, 256), 256>>>(near_dst, dd, ENEAR);
    make_inv<<<CDIV(NU, 256), 256>>>(du, inv_du, NU, 0);
    make_inv<<<CDIV(NR, 256), 256>>>(dr, inv_dr, NR, 0);
    make_inv<<<CDIV(NR, 256), 256>>>(ds, inv_ds, NR, 1);
    make_inv<<<CDIV(NR, 256), 256>>>(dd, inv_dd, NR, 1);
    scan3<<<3, 1024>>>(dr, offRD, NR, dd, offND, NR, du, offRS, NU);
    cudaMemcpyAsync(curRD, offRD, sizeof(int) * NR, cudaMemcpyDeviceToDevice);
    cudaMemcpyAsync(curND, offND, sizeof(int) * NR, cudaMemcpyDeviceToDevice);
    cudaMemcpyAsync(curRS, offRS, sizeof(int) * NU, cudaMemcpyDeviceToDevice);
    fill_bucket<<<CDIV(EREV, 256), 256>>>(rev_dst, rev_src, inv_dr, inv_du, curRD, ndRD, nmRD, EREV);
    fill_bucket<<<CDIV(ENEAR, 256), 256>>>(near_dst, near_src, inv_dd, inv_ds, curND, ndND, nmND, ENEAR);
    fill_bucket<<<CDIV(EREV, 256), 256>>>(rev_src, rev_dst, inv_du, inv_dr, curRS, ndRS, nmRS, EREV);

    gather_aggX<<<NR, 128>>>(x_user, agg1h, agg1l);
    cudaStreamWaitEvent(0, evPR, 0);
    gather_aggRR<<<NR, 64>>>(hrAf, agg1h, agg1l, 192, 128);
    cudaEventRecord(evAG1, 0);

    // ----- s2: layer 1 GEMMs -----
    wgemm2<<<gR, 256, GEMM_SMEM, s2>>>(hrAh, hrAl, wh + O_RU1, wl + O_RU1,
                                       tru1, nullptr, nullptr, nullptr,
                                       nullptr, nullptr, 0, NR, H);
    cudaEventRecord(evT1, s2);
    cudaStreamWaitEvent(s2, evAG1, 0);
    wgemm2<<<gR, 256, GEMM_SMEM, s2>>>(agg1h, agg1l, wh + O_WCOMB, wl + O_WCOMB,
                                       nullptr, hrBh, hrBl, hrBf,
                                       b1_ur, b1_rr, 1, NR, 768);
    cudaEventRecord(evR1, s2);
    wgemm2<<<gR, 256, GEMM_SMEM, s2>>>(hrBh, hrBl, wh + O_RU2, wl + O_RU2,
                                       tru2, nullptr, nullptr, nullptr,
                                       nullptr, nullptr, 0, NR, H);
    cudaEventRecord(evT2, s2);

    // ----- stream0: user gather L1, agg gathers L2 -----
    cudaStreamWaitEvent(0, evT1, 0);
    gather_user<<<NU, 64>>>(tru1, b1_ru, nullptr, nullptr, huBf);
    cudaStreamWaitEvent(0, evR1, 0);
    gather_aggRR<<<NR, 64>>>(hrBf, agg2h, agg2l, 128, 64);
    gather_aggU<<<NR, 64>>>(huBf, agg2h, agg2l, 128, 0);
    cudaEventRecord(evAG2, 0);

    // ----- s2: layer 2 CAT GEMM + rest output -----
    cudaStreamWaitEvent(s2, evAG2, 0);
    wgemm2<<<gR, 256, GEMM_SMEM, s2>>>(agg2h, agg2l, wh + O_CAT2, wl + O_CAT2,
                                       nullptr, hrAh, hrAl, nullptr,
                                       b2_ur, b2_rr, 1, NR, 2 * H);
    float* out = (float*)d_out;
    wgemm2<<<gR, 256, GEMM_SMEM, s2>>>(hrAh, hrAl, wh + O_OUTR, wl + O_OUTR,
                                       out + (size_t)NU * H, nullptr, nullptr, nullptr,
                                       nullptr, nullptr, 0, NR, H);
    cudaEventRecord(evJoin, s2);

    // ----- stream0: user gather L2 + user output -----
    cudaStreamWaitEvent(0, evT2, 0);
    gather_user<<<NU, 64>>>(tru2, b2_ru, huAh, huAl, nullptr);
    wgemm2<<<gU, 256, GEMM_SMEM>>>(huAh, huAl, wh + O_OUTU, wl + O_OUTU,
                                   out, nullptr, nullptr, nullptr,
                                   nullptr, nullptr, 0, NU, H);
    cudaStreamWaitEvent(0, evJoin, 0);
}

// round 17
// speedup vs baseline: 1.0728x; 1.0417x over previous
#include <cuda_runtime.h>
#include <cuda_bf16.h>
#include <mma.h>
#include <cstddef>
#include <cstdint>

using namespace nvcuda;

#define CDIV(a,b) (((a)+(b)-1)/(b))

constexpr int NU    = 50000;
constexpr int NR    = 20000;
constexpr int DIN   = 512;
constexpr int H     = 256;
constexpr int EREV  = 500000;
constexpr int ENEAR = 250000;

// ---------------- scratch (static device globals; no allocations) ----------
__device__ float g_tru1[(size_t)NR * H];
__device__ float g_tru2[(size_t)NR * H];
__device__ float g_huBf[(size_t)NU * H];
__device__ float g_hrAf[(size_t)NR * H];
__device__ float g_hrBf[(size_t)NR * H];
__device__ int   g_deg[NU + 3 * NR];
__device__ float g_inv_du[NU];
__device__ float g_inv_dr[NR];
__device__ float g_inv_ds[NR];
__device__ float g_inv_dd[NR];
// CSR buckets
__device__ int   g_offRD[NR + 1], g_offND[NR + 1], g_offRS[NU + 1];
__device__ int   g_curRD[NR],     g_curND[NR],     g_curRS[NU];
__device__ int   g_ndRD[EREV],   g_ndND[ENEAR],   g_ndRS[EREV];
__device__ float g_nmRD[EREV],   g_nmND[ENEAR],   g_nmRS[EREV];
// bf16 hi/lo GEMM operands
__device__ __nv_bfloat16 g_xrh[(size_t)NR * DIN], g_xrl[(size_t)NR * DIN];
__device__ __nv_bfloat16 g_huAh[(size_t)NU * H], g_huAl[(size_t)NU * H];
__device__ __nv_bfloat16 g_hrAh[(size_t)NR * H], g_hrAl[(size_t)NR * H];
__device__ __nv_bfloat16 g_hrBh[(size_t)NR * H], g_hrBl[(size_t)NR * H];
__device__ __nv_bfloat16 g_agg1h[(size_t)NR * 768], g_agg1l[(size_t)NR * 768];
__device__ __nv_bfloat16 g_agg2h[(size_t)NR * 512], g_agg2l[(size_t)NR * 512];
constexpr int WTOT = 917504;
__device__ __nv_bfloat16 g_wh[WTOT], g_wl[WTOT];

// ---------------- helpers ----------------------------------------------------
__device__ __forceinline__ uint32_t smem_u32(const void* p) {
    uint32_t a;
    asm("{ .reg .u64 t; cvta.to.shared.u64 t, %1; cvt.u32.u64 %0, t; }" : "=r"(a) : "l"(p));
    return a;
}
__device__ __forceinline__ void cp16(uint32_t dst, const void* src, bool ok) {
    int sz = ok ? 16 : 0;
    asm volatile("cp.async.cg.shared.global [%0], [%1], 16, %2;"
                 :: "r"(dst), "l"(src), "r"(sz) : "memory");
}
#define CP_COMMIT() asm volatile("cp.async.commit_group;" ::: "memory")
#define CP_WAIT1()  asm volatile("cp.async.wait_group 1;" ::: "memory")

__device__ __forceinline__ uint2 split_pack(float4 v) {
    __nv_bfloat16 h0 = __float2bfloat16_rn(v.x), h1 = __float2bfloat16_rn(v.y);
    __nv_bfloat16 h2 = __float2bfloat16_rn(v.z), h3 = __float2bfloat16_rn(v.w);
    __nv_bfloat162 a = __halves2bfloat162(h0, h1);
    __nv_bfloat162 b = __halves2bfloat162(h2, h3);
    uint2 r;
    r.x = *(uint32_t*)&a; r.y = *(uint32_t*)&b;
    return r;
}
__device__ __forceinline__ uint2 split_pack_lo(float4 v, uint2 hi) {
    __nv_bfloat162 a = *(__nv_bfloat162*)&hi.x;
    __nv_bfloat162 b = *(__nv_bfloat162*)&hi.y;
    float4 r = make_float4(v.x - __bfloat162float(__low2bfloat16(a)),
                           v.y - __bfloat162float(__high2bfloat16(a)),
                           v.z - __bfloat162float(__low2bfloat16(b)),
                           v.w - __bfloat162float(__high2bfloat16(b)));
    return split_pack(r);
}

// ---------------- fused split-everything kernel -------------------------------
// Splits 10 weight matrices into g_wh/g_wl at their scratch offsets, plus
// x_rest into g_xrh/g_xrl — one launch instead of 11.
constexpr int WTOT4 = 196608;
constexpr int XR4   = NR * DIN / 4;   // 2,560,000

__global__ void split_all(const float* s0, const float* s1, const float* s2,
                          const float* s3, const float* s4, const float* s5,
                          const float* s6, const float* s7, const float* s8,
                          const float* s9, const float* xr,
                          __nv_bfloat16* __restrict__ wh, __nv_bfloat16* __restrict__ wl,
                          __nv_bfloat16* __restrict__ xrh, __nv_bfloat16* __restrict__ xrl) {
    const int wend[10] = {32768, 49152, 81920, 98304, 114688, 131072, 147456, 163840, 180224, 196608};
    const int wdst[10] = {0, 98304, 32768, 65536, 81920, 147456, 163840, 180224, 196608, 212992};
    int gid = blockIdx.x * 256 + threadIdx.x;
    if (gid >= WTOT4) {
        int j = gid - WTOT4;
        if (j >= XR4) return;
        float4 v = ((const float4*)xr)[j];
        uint2 hi = split_pack(v);
        uint2 lo = split_pack_lo(v, hi);
        ((uint2*)xrh)[j] = hi;
        ((uint2*)xrl)[j] = lo;
        return;
    }
    const float* srcs[10] = {s0, s1, s2, s3, s4, s5, s6, s7, s8, s9};
    int job = 0, beg = 0;
#pragma unroll
    for (int k = 0; k < 10; k++)
        if (gid >= wend[k]) { job = k + 1; beg = wend[k]; }
    int j = gid - beg;
    float4 v = ((const float4*)srcs[job])[j];
    uint2 hi = split_pack(v);
    uint2 lo = split_pack_lo(v, hi);
    ((uint2*)wh)[wdst[job] + j] = hi;
    ((uint2*)wl)[wdst[job] + j] = lo;
}

// ---------------- double-buffered bf16-split wmma GEMM ----------------------
constexpr int BM = 128, BN = 256, BK = 32;
constexpr int LDA = BK + 8;
constexpr int LDB = BN + 8;
constexpr int E_AH = 0;
constexpr int E_AL = E_AH + BM * LDA;
constexpr int E_BH = E_AL + BM * LDA;
constexpr int E_BL = E_BH + BK * LDB;
constexpr int STAGE_E = E_BL + BK * LDB;
constexpr int GEMM_SMEM = 2 * STAGE_E * 2;

__global__ __launch_bounds__(256, 1) void wgemm2(const __nv_bfloat16* __restrict__ Ahg,
                                                 const __nv_bfloat16* __restrict__ Alg,
                                                 const __nv_bfloat16* __restrict__ Bhg,
                                                 const __nv_bfloat16* __restrict__ Blg,
                                                 float* __restrict__ C,
                                                 __nv_bfloat16* __restrict__ Ch,
                                                 __nv_bfloat16* __restrict__ Cl,
                                                 float* __restrict__ Cf,
                                                 const float* __restrict__ bias0,
                                                 const float* __restrict__ bias1,
                                                 int do_relu,
                                                 int M, int K) {
    extern __shared__ __nv_bfloat16 sm[];
    uint32_t sbase = smem_u32(sm);

    int tid  = threadIdx.x;
    int wid  = tid >> 5;
    int lane = tid & 31;
    int row0 = blockIdx.y * BM;
    int wm   = wid >> 2;
    int wn   = wid & 3;

    wmma::fragment<wmma::accumulator, 16, 16, 16, float> acc[4][4];
#pragma unroll
    for (int mi = 0; mi < 4; mi++)
#pragma unroll
        for (int ni = 0; ni < 4; ni++) wmma::fill_fragment(acc[mi][ni], 0.f);

    auto load_stage = [&](int st, int k0) {
        uint32_t base = sbase + st * (STAGE_E * 2);
#pragma unroll
        for (int q = 0; q < 2; q++) {
            int i   = tid + 256 * q;
            int row = i >> 2;
            int c8  = (i & 3) << 3;
            bool ok = (row0 + row) < M;
            size_t off = (size_t)(ok ? row0 + row : 0) * K + k0 + c8;
            uint32_t d = base + (row * LDA + c8) * 2;
            cp16(d, Ahg + off, ok);
            cp16(d + E_AL * 2, Alg + off, ok);
        }
#pragma unroll
        for (int q = 0; q < 4; q++) {
            int i  = tid + 256 * q;
            int kk = i >> 5;
            int c8 = (i & 31) << 3;
            size_t off = (size_t)(k0 + kk) * 256 + c8;
            uint32_t d = base + E_BH * 2 + (kk * LDB + c8) * 2;
            cp16(d, Bhg + off, true);
            cp16(d + (E_BL - E_BH) * 2, Blg + off, true);
        }
    };

    int NC = K / BK;
    load_stage(0, 0);
    CP_COMMIT();

    for (int c = 0; c < NC; c++) {
        if (c + 1 < NC) load_stage((c + 1) & 1, (c + 1) * BK);
        CP_COMMIT();
        CP_WAIT1();
        __syncthreads();

        const __nv_bfloat16* sAh = sm + (c & 1) * STAGE_E + E_AH;
        const __nv_bfloat16* sAl = sm + (c & 1) * STAGE_E + E_AL;
        const __nv_bfloat16* sBh = sm + (c & 1) * STAGE_E + E_BH;
        const __nv_bfloat16* sBl = sm + (c & 1) * STAGE_E + E_BL;

#pragma unroll
        for (int kk = 0; kk < BK; kk += 16) {
            wmma::fragment<wmma::matrix_a, 16, 16, 16, __nv_bfloat16, wmma::row_major> ah[4], al[4];
#pragma unroll
            for (int mi = 0; mi < 4; mi++) {
                wmma::load_matrix_sync(ah[mi], sAh + (wm * 64 + mi * 16) * LDA + kk, LDA);
                wmma::load_matrix_sync(al[mi], sAl + (wm * 64 + mi * 16) * LDA + kk, LDA);
            }
#pragma unroll
            for (int ni = 0; ni < 4; ni++) {
                wmma::fragment<wmma::matrix_b, 16, 16, 16, __nv_bfloat16, wmma::row_major> bh, bl;
                wmma::load_matrix_sync(bh, sBh + kk * LDB + wn * 64 + ni * 16, LDB);
                wmma::load_matrix_sync(bl, sBl + kk * LDB + wn * 64 + ni * 16, LDB);
#pragma unroll
                for (int mi = 0; mi < 4; mi++) {
                    wmma::mma_sync(acc[mi][ni], ah[mi], bh, acc[mi][ni]);
                    wmma::mma_sync(acc[mi][ni], al[mi], bh, acc[mi][ni]);
                    wmma::mma_sync(acc[mi][ni], ah[mi], bl, acc[mi][ni]);
                }
            }
        }
        __syncthreads();
    }

    if (Ch != nullptr) {
        float* stage = (float*)sm + wid * 512;
#pragma unroll
        for (int mi = 0; mi < 4; mi++)
#pragma unroll
            for (int ni = 0; ni < 4; ni++) {
                wmma::store_matrix_sync(stage, acc[mi][ni], 20, wmma::mem_row_major);
                __syncwarp();
#pragma unroll
                for (int jj = 0; jj < 4; jj++) {
                    int e2 = lane * 4 + jj;
                    int r  = e2 >> 3;
                    int c0 = (e2 & 7) * 2;
                    int row = row0 + wm * 64 + mi * 16 + r;
                    if (row < M) {
                        int col = wn * 64 + ni * 16 + c0;
                        float v0 = stage[r * 20 + c0], v1 = stage[r * 20 + c0 + 1];
                        if (bias0) { v0 += bias0[col]; v1 += bias0[col + 1]; }
                        if (bias1) { v0 += bias1[col]; v1 += bias1[col + 1]; }
                        if (do_relu) { v0 = fmaxf(v0, 0.f); v1 = fmaxf(v1, 0.f); }
                        __nv_bfloat16 h0 = __float2bfloat16_rn(v0);
                        __nv_bfloat16 h1 = __float2bfloat16_rn(v1);
                        __nv_bfloat16 l0 = __float2bfloat16_rn(v0 - __bfloat162float(h0));
                        __nv_bfloat16 l1 = __float2bfloat16_rn(v1 - __bfloat162float(h1));
                        size_t off = (size_t)row * 256 + col;
                        *(__nv_bfloat162*)(Ch + off) = __halves2bfloat162(h0, h1);
                        *(__nv_bfloat162*)(Cl + off) = __halves2bfloat162(l0, l1);
                        if (Cf) { Cf[off] = v0; Cf[off + 1] = v1; }
                    }
                }
                __syncwarp();
            }
    } else if (row0 + BM <= M) {
#pragma unroll
        for (int mi = 0; mi < 4; mi++)
#pragma unroll
            for (int ni = 0; ni < 4; ni++) {
                float* cp = C + (size_t)(row0 + wm * 64 + mi * 16) * 256
                              + wn * 64 + ni * 16;
                wmma::store_matrix_sync(cp, acc[mi][ni], 256, wmma::mem_row_major);
            }
    } else {
        float* stage = (float*)sm + wid * 512;
#pragma unroll
        for (int mi = 0; mi < 4; mi++)
#pragma unroll
            for (int ni = 0; ni < 4; ni++) {
                wmma::store_matrix_sync(stage, acc[mi][ni], 20, wmma::mem_row_major);
                __syncwarp();
#pragma unroll
                for (int j = 0; j < 8; j++) {
                    int e   = lane * 8 + j;
                    int r   = e >> 4, cc = e & 15;
                    int row = row0 + wm * 64 + mi * 16 + r;
                    if (row < M)
                        C[(size_t)row * 256 + wn * 64 + ni * 16 + cc] =
                            stage[r * 20 + cc];
                }
                __syncwarp();
            }
    }
}

// ---------------- CSR build kernels -----------------------------------------
__global__ void count_deg(const int* __restrict__ idx, int* __restrict__ deg, int E) {
    int i = blockIdx.x * 256 + threadIdx.x;
    if (i < E) atomicAdd(&deg[idx[i]], 1);
}

__global__ void make_inv(const int* __restrict__ deg, float* __restrict__ inv, int n, int add) {
    int i = blockIdx.x * 256 + threadIdx.x;
    if (i < n) {
        int d = deg[i] + add;
        inv[i] = d > 0 ? rsqrtf((float)d) : 0.f;
    }
}

__global__ __launch_bounds__(1024) void scan3(const int* c0, int* o0, int n0,
                                              const int* c1, int* o1, int n1,
                                              const int* c2, int* o2, int n2) {
    const int* cnt = blockIdx.x == 0 ? c0 : blockIdx.x == 1 ? c1 : c2;
    int* off = blockIdx.x == 0 ? o0 : blockIdx.x == 1 ? o1 : o2;
    int n    = blockIdx.x == 0 ? n0 : blockIdx.x == 1 ? n1 : n2;
    __shared__ int tmp[1024];
    __shared__ int carry;
    if (threadIdx.x == 0) carry = 0;
    __syncthreads();
    for (int base = 0; base < n; base += 1024) {
        int i = base + (int)threadIdx.x;
        int v = (i < n) ? cnt[i] : 0;
        tmp[threadIdx.x] = v;
        __syncthreads();
#pragma unroll
        for (int s = 1; s < 1024; s <<= 1) {
            int t = (threadIdx.x >= (unsigned)s) ? tmp[threadIdx.x - s] : 0;
            __syncthreads();
            tmp[threadIdx.x] += t;
            __syncthreads();
        }
        if (i < n) off[i] = carry + tmp[threadIdx.x] - v;
        __syncthreads();
        if (threadIdx.x == 0) carry += tmp[1023];
        __syncthreads();
    }
    if (threadIdx.x == 0) off[n] = carry;
}

__global__ void fill_bucket(const int* __restrict__ key, const int* __restrict__ other,
                            const float* __restrict__ inv_k, const float* __restrict__ inv_o,
                            int* __restrict__ cursor,
                            int* __restrict__ nodes, float* __restrict__ norms, int E) {
    int i = blockIdx.x * 256 + threadIdx.x;
    if (i >= E) return;
    int k = key[i], o = other[i];
    int pos = atomicAdd(&cursor[k], 1);
    nodes[pos] = o;
    norms[pos] = inv_k[k] * inv_o[o];
}

// ---------------- gathers -----------------------------------------------------
__global__ __launch_bounds__(128) void gather_aggX(const float* __restrict__ xu,
                                                   __nv_bfloat16* __restrict__ aggh,
                                                   __nv_bfloat16* __restrict__ aggl) {
    int row = blockIdx.x;
    int c   = threadIdx.x;
    float4 acc = make_float4(0.f, 0.f, 0.f, 0.f);
    int e = g_offRD[row], e1 = g_offRD[row + 1];
    for (; e < e1; e++) {
        int s = g_ndRD[e];
        float n = g_nmRD[e];
        float4 v = ((const float4*)xu)[(size_t)s * 128 + c];
        acc.x += v.x * n; acc.y += v.y * n; acc.z += v.z * n; acc.w += v.w * n;
    }
    uint2 hi = split_pack(acc);
    uint2 lo = split_pack_lo(acc, hi);
    ((uint2*)aggh)[(size_t)row * 192 + c] = hi;
    ((uint2*)aggl)[(size_t)row * 192 + c] = lo;
}

__global__ __launch_bounds__(64) void gather_aggU(const float* __restrict__ huf,
                                                  __nv_bfloat16* __restrict__ aggh,
                                                  __nv_bfloat16* __restrict__ aggl,
                                                  int stride_u2, int off_u2) {
    int row = blockIdx.x;
    int c   = threadIdx.x;
    float4 acc = make_float4(0.f, 0.f, 0.f, 0.f);
    int e = g_offRD[row], e1 = g_offRD[row + 1];
    for (; e + 1 < e1; e += 2) {
        int s0 = g_ndRD[e], s1 = g_ndRD[e + 1];
        float n0 = g_nmRD[e], n1 = g_nmRD[e + 1];
        float4 v0 = ((const float4*)huf)[(size_t)s0 * 64 + c];
        float4 v1 = ((const float4*)huf)[(size_t)s1 * 64 + c];
        acc.x += v0.x * n0 + v1.x * n1; acc.y += v0.y * n0 + v1.y * n1;
        acc.z += v0.z * n0 + v1.z * n1; acc.w += v0.w * n0 + v1.w * n1;
    }
    if (e < e1) {
        int s0 = g_ndRD[e]; float n0 = g_nmRD[e];
        float4 v0 = ((const float4*)huf)[(size_t)s0 * 64 + c];
        acc.x += v0.x * n0; acc.y += v0.y * n0; acc.z += v0.z * n0; acc.w += v0.w * n0;
    }
    uint2 hi = split_pack(acc);
    uint2 lo = split_pack_lo(acc, hi);
    ((uint2*)aggh)[(size_t)row * stride_u2 + off_u2 + c] = hi;
    ((uint2*)aggl)[(size_t)row * stride_u2 + off_u2 + c] = lo;
}

__global__ __launch_bounds__(64) void gather_aggRR(const float* __restrict__ hrf,
                                                   __nv_bfloat16* __restrict__ aggh,
                                                   __nv_bfloat16* __restrict__ aggl,
                                                   int stride_u2, int off_u2) {
    int row = blockIdx.x;
    int c   = threadIdx.x;
    float coef = g_inv_ds[row] * g_inv_dd[row];
    float4 own = ((const float4*)hrf)[(size_t)row * 64 + c];
    float4 acc = make_float4(own.x * coef, own.y * coef, own.z * coef, own.w * coef);
    int e = g_offND[row], e1 = g_offND[row + 1];
    for (; e + 1 < e1; e += 2) {
        int s0 = g_ndND[e], s1 = g_ndND[e + 1];
        float n0 = g_nmND[e], n1 = g_nmND[e + 1];
        float4 v0 = ((const float4*)hrf)[(size_t)s0 * 64 + c];
        float4 v1 = ((const float4*)hrf)[(size_t)s1 * 64 + c];
        acc.x += v0.x * n0 + v1.x * n1; acc.y += v0.y * n0 + v1.y * n1;
        acc.z += v0.z * n0 + v1.z * n1; acc.w += v0.w * n0 + v1.w * n1;
    }
    if (e < e1) {
        int s0 = g_ndND[e]; float n0 = g_nmND[e];
        float4 v0 = ((const float4*)hrf)[(size_t)s0 * 64 + c];
        acc.x += v0.x * n0; acc.y += v0.y * n0; acc.z += v0.z * n0; acc.w += v0.w * n0;
    }
    uint2 hi = split_pack(acc);
    uint2 lo = split_pack_lo(acc, hi);
    ((uint2*)aggh)[(size_t)row * stride_u2 + off_u2 + c] = hi;
    ((uint2*)aggl)[(size_t)row * stride_u2 + off_u2 + c] = lo;
}

__global__ __launch_bounds__(64) void gather_user(const float* __restrict__ tru,
                                                  const float* __restrict__ bru,
                                                  __nv_bfloat16* __restrict__ hh,
                                                  __nv_bfloat16* __restrict__ hl,
                                                  float* __restrict__ hf) {
    int row = blockIdx.x;
    int c   = threadIdx.x;
    float4 acc = ((const float4*)bru)[c];

    int e = g_offRS[row], e1 = g_offRS[row + 1];
    for (; e + 1 < e1; e += 2) {
        int s0 = g_ndRS[e], s1 = g_ndRS[e + 1];
        float n0 = g_nmRS[e], n1 = g_nmRS[e + 1];
        float4 v0 = ((const float4*)tru)[(size_t)s0 * 64 + c];
        float4 v1 = ((const float4*)tru)[(size_t)s1 * 64 + c];
        acc.x += v0.x * n0 + v1.x * n1; acc.y += v0.y * n0 + v1.y * n1;
        acc.z += v0.z * n0 + v1.z * n1; acc.w += v0.w * n0 + v1.w * n1;
    }
    if (e < e1) {
        int s0 = g_ndRS[e]; float n0 = g_nmRS[e];
        float4 v0 = ((const float4*)tru)[(size_t)s0 * 64 + c];
        acc.x += v0.x * n0; acc.y += v0.y * n0; acc.z += v0.z * n0; acc.w += v0.w * n0;
    }

    acc = make_float4(fmaxf(acc.x, 0.f), fmaxf(acc.y, 0.f),
                      fmaxf(acc.z, 0.f), fmaxf(acc.w, 0.f));
    if (hh) {
        uint2 hi = split_pack(acc);
        uint2 lo = split_pack_lo(acc, hi);
        ((uint2*)hh)[(size_t)row * 64 + c] = hi;
        ((uint2*)hl)[(size_t)row * 64 + c] = lo;
    }
    if (hf) ((float4*)hf)[(size_t)row * 64 + c] = acc;
}

// ---------------- host orchestration ----------------------------------------
extern "C" void kernel_launch(void* const* d_in, const int* in_sizes, int n_in,
                              void* d_out, int out_size) {
    const float* x_user    = (const float*)d_in[0];
    const float* x_rest    = (const float*)d_in[1];
    const int*   rev_src   = (const int*)d_in[2];
    const int*   rev_dst   = (const int*)d_in[3];
    const int*   near_src  = (const int*)d_in[4];
    const int*   near_dst  = (const int*)d_in[5];
    const float* Win_user  = (const float*)d_in[6];
    const float* Win_rest  = (const float*)d_in[7];
    const float* W1_ur = (const float*)d_in[8];
    const float* b1_ur = (const float*)d_in[9];
    const float* W1_ru = (const float*)d_in[10];
    const float* b1_ru = (const float*)d_in[11];
    const float* W1_rr = (const float*)d_in[12];
    const float* b1_rr = (const float*)d_in[13];
    const float* W2_ur = (const float*)d_in[14];
    const float* b2_ur = (const float*)d_in[15];
    const float* W2_ru = (const float*)d_in[16];
    const float* b2_ru = (const float*)d_in[17];
    const float* W2_rr = (const float*)d_in[18];
    const float* b2_rr = (const float*)d_in[19];
    const float* Wout_user = (const float*)d_in[20];
    const float* Wout_rest = (const float*)d_in[21];

    cudaFuncSetAttribute(wgemm2, cudaFuncAttributeMaxDynamicSharedMemorySize, GEMM_SMEM);

    static cudaStream_t s2 = nullptr;
    static cudaEvent_t evFork, evPR, evT1, evR1, evT2, evAG1, evAG2, evJoin;
    if (!s2) {
        cudaStreamCreateWithFlags(&s2, cudaStreamNonBlocking);
        cudaEventCreateWithFlags(&evFork, cudaEventDisableTiming);
        cudaEventCreateWithFlags(&evPR,   cudaEventDisableTiming);
        cudaEventCreateWithFlags(&evT1,   cudaEventDisableTiming);
        cudaEventCreateWithFlags(&evR1,   cudaEventDisableTiming);
        cudaEventCreateWithFlags(&evT2,   cudaEventDisableTiming);
        cudaEventCreateWithFlags(&evAG1,  cudaEventDisableTiming);
        cudaEventCreateWithFlags(&evAG2,  cudaEventDisableTiming);
        cudaEventCreateWithFlags(&evJoin, cudaEventDisableTiming);
    }

    float *tru1, *tru2, *huBf, *hrAf, *hrBf;
    float *inv_du, *inv_dr, *inv_ds, *inv_dd;
    int *deg, *offRD, *offND, *offRS, *curRD, *curND, *curRS, *ndRD, *ndND, *ndRS;
    float *nmRD, *nmND, *nmRS;
    __nv_bfloat16 *xrh, *xrl, *wh, *wl, *agg1h, *agg1l, *agg2h, *agg2l;
    __nv_bfloat16 *huAh, *huAl, *hrAh, *hrAl, *hrBh, *hrBl;
    cudaGetSymbolAddress((void**)&tru1, g_tru1);
    cudaGetSymbolAddress((void**)&tru2, g_tru2);
    cudaGetSymbolAddress((void**)&huBf, g_huBf);
    cudaGetSymbolAddress((void**)&hrAf, g_hrAf);
    cudaGetSymbolAddress((void**)&hrBf, g_hrBf);
    cudaGetSymbolAddress((void**)&inv_du, g_inv_du);
    cudaGetSymbolAddress((void**)&inv_dr, g_inv_dr);
    cudaGetSymbolAddress((void**)&inv_ds, g_inv_ds);
    cudaGetSymbolAddress((void**)&inv_dd, g_inv_dd);
    cudaGetSymbolAddress((void**)&deg, g_deg);
    cudaGetSymbolAddress((void**)&offRD, g_offRD);
    cudaGetSymbolAddress((void**)&offND, g_offND);
    cudaGetSymbolAddress((void**)&offRS, g_offRS);
    cudaGetSymbolAddress((void**)&curRD, g_curRD);
    cudaGetSymbolAddress((void**)&curND, g_curND);
    cudaGetSymbolAddress((void**)&curRS, g_curRS);
    cudaGetSymbolAddress((void**)&ndRD, g_ndRD);
    cudaGetSymbolAddress((void**)&ndND, g_ndND);
    cudaGetSymbolAddress((void**)&ndRS, g_ndRS);
    cudaGetSymbolAddress((void**)&nmRD, g_nmRD);
    cudaGetSymbolAddress((void**)&nmND, g_nmND);
    cudaGetSymbolAddress((void**)&nmRS, g_nmRS);
    cudaGetSymbolAddress((void**)&xrh, g_xrh);
    cudaGetSymbolAddress((void**)&xrl, g_xrl);
    cudaGetSymbolAddress((void**)&huAh, g_huAh);
    cudaGetSymbolAddress((void**)&huAl, g_huAl);
    cudaGetSymbolAddress((void**)&hrAh, g_hrAh);
    cudaGetSymbolAddress((void**)&hrAl, g_hrAl);
    cudaGetSymbolAddress((void**)&hrBh, g_hrBh);
    cudaGetSymbolAddress((void**)&hrBl, g_hrBl);
    cudaGetSymbolAddress((void**)&agg1h, g_agg1h);
    cudaGetSymbolAddress((void**)&agg1l, g_agg1l);
    cudaGetSymbolAddress((void**)&agg2h, g_agg2h);
    cudaGetSymbolAddress((void**)&agg2l, g_agg2l);
    cudaGetSymbolAddress((void**)&wh, g_wh);
    cudaGetSymbolAddress((void**)&wl, g_wl);

    int* du = deg;
    int* dr = deg + NU;
    int* ds = dr + NR;
    int* dd = ds + NR;

    const int O_WIN_U = 0;
    const int O_WIN_R = 131072;
    const int O_RU1   = 262144;
    const int O_RU2   = 327680;
    const int O_W1UR  = 393216;
    const int O_WCOMB = 458752;
    const int O_CAT2  = 655360;
    const int O_OUTU  = 786432;
    const int O_OUTR  = 851968;

    dim3 gU(1, CDIV(NU, BM));
    dim3 gR(1, CDIV(NR, BM));
    dim3 gW(1, CDIV(512, BM));

    // ===== fork s2 =====
    cudaEventRecord(evFork, 0);
    cudaStreamWaitEvent(s2, evFork, 0);

    // ----- s2: ONE fused split (10 weights + x_rest), Wcomb, rest projection -----
    split_all<<<CDIV(WTOT4 + XR4, 256), 256, 0, s2>>>(
        Win_user, W1_ur, Win_rest, W1_ru, W2_ru, W1_rr, W2_ur, W2_rr,
        Wout_user, Wout_rest, x_rest, wh, wl, xrh, xrl);
    wgemm2<<<gW, 256, GEMM_SMEM, s2>>>(wh + O_WIN_U, wl + O_WIN_U, wh + O_W1UR, wl + O_W1UR,
                                       nullptr, wh + O_WCOMB, wl + O_WCOMB, nullptr,
                                       nullptr, nullptr, 0, 512, 256);
    wgemm2<<<gR, 256, GEMM_SMEM, s2>>>(xrh, xrl, wh + O_WIN_R, wl + O_WIN_R,
                                       nullptr, hrAh, hrAl, hrAf,
                                       nullptr, nullptr, 0, NR, DIN);
    cudaEventRecord(evPR, s2);

    // ----- stream0: CSR build, then raw-input ur-gather -----
    cudaMemsetAsync(deg, 0, sizeof(int) * (NU + 3 * NR));
    count_deg<<<CDIV(EREV, 256), 256>>>(rev_src, du, EREV);
    count_deg<<<CDIV(EREV, 256), 256>>>(rev_dst, dr, EREV);
    count_deg<<<CDIV(ENEAR, 256), 256>>>(near_src, ds, ENEAR);
    count_deg<<<CDIV(ENEAR, 256), 256>>>(near_dst, dd, ENEAR);
    make_inv<<<CDIV(NU, 256), 256>>>(du, inv_du, NU, 0);
    make_inv<<<CDIV(NR, 256), 256>>>(dr, inv_dr, NR, 0);
    make_inv<<<CDIV(NR, 256), 256>>>(ds, inv_ds, NR, 1);
    make_inv<<<CDIV(NR, 256), 256>>>(dd, inv_dd, NR, 1);
    scan3<<<3, 1024>>>(dr, offRD, NR, dd, offND, NR, du, offRS, NU);
    cudaMemcpyAsync(curRD, offRD, sizeof(int) * NR, cudaMemcpyDeviceToDevice);
    cudaMemcpyAsync(curND, offND, sizeof(int) * NR, cudaMemcpyDeviceToDevice);
    cudaMemcpyAsync(curRS, offRS, sizeof(int) * NU, cudaMemcpyDeviceToDevice);
    fill_bucket<<<CDIV(EREV, 256), 256>>>(rev_dst, rev_src, inv_dr, inv_du, curRD, ndRD, nmRD, EREV);
    fill_bucket<<<CDIV(ENEAR, 256), 256>>>(near_dst, near_src, inv_dd, inv_ds, curND, ndND, nmND, ENEAR);
    fill_bucket<<<CDIV(EREV, 256), 256>>>(rev_src, rev_dst, inv_du, inv_dr, curRS, ndRS, nmRS, EREV);

    gather_aggX<<<NR, 128>>>(x_user, agg1h, agg1l);
    cudaStreamWaitEvent(0, evPR, 0);
    gather_aggRR<<<NR, 64>>>(hrAf, agg1h, agg1l, 192, 128);
    cudaEventRecord(evAG1, 0);

    // ----- s2: layer 1 GEMMs -----
    wgemm2<<<gR, 256, GEMM_SMEM, s2>>>(hrAh, hrAl, wh + O_RU1, wl + O_RU1,
                                       tru1, nullptr, nullptr, nullptr,
                                       nullptr, nullptr, 0, NR, H);
    cudaEventRecord(evT1, s2);
    cudaStreamWaitEvent(s2, evAG1, 0);
    wgemm2<<<gR, 256, GEMM_SMEM, s2>>>(agg1h, agg1l, wh + O_WCOMB, wl + O_WCOMB,
                                       nullptr, hrBh, hrBl, hrBf,
                                       b1_ur, b1_rr, 1, NR, 768);
    cudaEventRecord(evR1, s2);
    wgemm2<<<gR, 256, GEMM_SMEM, s2>>>(hrBh, hrBl, wh + O_RU2, wl + O_RU2,
                                       tru2, nullptr, nullptr, nullptr,
                                       nullptr, nullptr, 0, NR, H);
    cudaEventRecord(evT2, s2);

    // ----- stream0: user gather L1, agg gathers L2 -----
    cudaStreamWaitEvent(0, evT1, 0);
    gather_user<<<NU, 64>>>(tru1, b1_ru, nullptr, nullptr, huBf);
    cudaStreamWaitEvent(0, evR1, 0);
    gather_aggRR<<<NR, 64>>>(hrBf, agg2h, agg2l, 128, 64);
    gather_aggU<<<NR, 64>>>(huBf, agg2h, agg2l, 128, 0);
    cudaEventRecord(evAG2, 0);

    // ----- s2: layer 2 CAT GEMM + rest output -----
    cudaStreamWaitEvent(s2, evAG2, 0);
    wgemm2<<<gR, 256, GEMM_SMEM, s2>>>(agg2h, agg2l, wh + O_CAT2, wl + O_CAT2,
                                       nullptr, hrAh, hrAl, nullptr,
                                       b2_ur, b2_rr, 1, NR, 2 * H);
    float* out = (float*)d_out;
    wgemm2<<<gR, 256, GEMM_SMEM, s2>>>(hrAh, hrAl, wh + O_OUTR, wl + O_OUTR,
                                       out + (size_t)NU * H, nullptr, nullptr, nullptr,
                                       nullptr, nullptr, 0, NR, H);
    cudaEventRecord(evJoin, s2);

    // ----- stream0: user gather L2 + user output -----
    cudaStreamWaitEvent(0, evT2, 0);
    gather_user<<<NU, 64>>>(tru2, b2_ru, huAh, huAl, nullptr);
    wgemm2<<<gU, 256, GEMM_SMEM>>>(huAh, huAl, wh + O_OUTU, wl + O_OUTU,
                                   out, nullptr, nullptr, nullptr,
                                   nullptr, nullptr, 0, NU, H);
    cudaStreamWaitEvent(0, evJoin, 0);
}